// round 1
// baseline (speedup 1.0000x reference)
#include <cuda_runtime.h>

// ---------------------------------------------------------------------------
// Problem constants
// ---------------------------------------------------------------------------
namespace {
constexpr int kB   = 2;
constexpr int kS   = 2048;
constexpr int kD   = 1024;
constexpr int kH   = 16;
constexpr int kHD  = 64;
constexpr int kDFF = 4096;
constexpr int kM   = kB * kS;   // 4096 rows
constexpr float kEps = 1e-5f;
}

// ---------------------------------------------------------------------------
// Device scratch (static __device__ globals -- no allocation anywhere)
// ---------------------------------------------------------------------------
__device__ float g_wr[3][(size_t)kD * kD];                 // repacked Wq/Wk/Wv
__device__ float g_q[(size_t)kM * kD];
__device__ float g_k[(size_t)kM * kD];
__device__ float g_v[(size_t)kM * kD];
__device__ float g_scores[(size_t)kB * kH * kS * kS];      // 512 MB
__device__ float g_attn[(size_t)kM * kD];
__device__ float g_proj[(size_t)kM * kD];
__device__ float g_y[(size_t)kM * kD];
__device__ float g_ff1[(size_t)kM * kDFF];                 // 64 MB
__device__ float g_ff2[(size_t)kM * kD];

// ---------------------------------------------------------------------------
// Generic tiled SGEMM.
//   C[m][n] = alpha * sum_k A[m][k] * B[k][n]   (TRANSB=false, B is KxN)
//   C[m][n] = alpha * sum_k A[m][k] * B[n][k]   (TRANSB=true,  B is NxK)
// Optional bias[n] add and ReLU. Batched via blockIdx.z with split strides:
//   base += (z / bdiv) * s?1 + (z % bdiv) * s?2
// Requirements (guaranteed by call sites): M % BM == 0, N % BN == 0,
// K % 16 == 0, all pointers/leading dims 16B aligned.
// ---------------------------------------------------------------------------
template <int BM, int BN, int TM, int TN, bool TRANSB, bool RELU, bool BIAS>
__global__ __launch_bounds__(256)
void sgemm_kernel(const float* __restrict__ A, const float* __restrict__ Bm,
                  const float* __restrict__ bias, float* __restrict__ C,
                  int M, int N, int K, int lda, int ldb, int ldc,
                  long long sA1, long long sA2,
                  long long sB1, long long sB2,
                  long long sC1, long long sC2,
                  int bdiv, float alpha)
{
    constexpr int BK  = 16;
    constexpr int PAD = 4;
    __shared__ float As[BK][BM + PAD];
    __shared__ float Bs[BK][BN + PAD];

    const int z  = blockIdx.z;
    const int zb = z / bdiv;
    const int zh = z - zb * bdiv;
    A  += zb * sA1 + zh * sA2;
    Bm += zb * sB1 + zh * sB2;
    C  += zb * sC1 + zh * sC2;

    const int m0  = blockIdx.y * BM;
    const int n0  = blockIdx.x * BN;
    const int tid = threadIdx.x;
    const int tx  = tid & 15;       // 16 columns of threads
    const int ty  = tid >> 4;       // 16 rows of threads

    float acc[TM][TN];
#pragma unroll
    for (int i = 0; i < TM; ++i)
#pragma unroll
        for (int j = 0; j < TN; ++j) acc[i][j] = 0.0f;

    for (int k0 = 0; k0 < K; k0 += BK) {
        // ---- load A tile: BM x BK (k contiguous in gmem) ----
#pragma unroll
        for (int it = 0; it < (BM * BK) / (4 * 256); ++it) {
            int idx = tid + it * 256;
            int m   = idx >> 2;            // 4 float4 per row (BK=16)
            int kq  = (idx & 3) * 4;
            float4 vv = *reinterpret_cast<const float4*>(
                A + (long long)(m0 + m) * lda + k0 + kq);
            As[kq + 0][m] = vv.x;
            As[kq + 1][m] = vv.y;
            As[kq + 2][m] = vv.z;
            As[kq + 3][m] = vv.w;
        }
        // ---- load B tile ----
        if (TRANSB) {
#pragma unroll
            for (int it = 0; it < (BN * BK) / (4 * 256); ++it) {
                int idx = tid + it * 256;
                int n   = idx >> 2;
                int kq  = (idx & 3) * 4;
                float4 vv = *reinterpret_cast<const float4*>(
                    Bm + (long long)(n0 + n) * ldb + k0 + kq);
                Bs[kq + 0][n] = vv.x;
                Bs[kq + 1][n] = vv.y;
                Bs[kq + 2][n] = vv.z;
                Bs[kq + 3][n] = vv.w;
            }
        } else {
#pragma unroll
            for (int it = 0; it < (BN * BK) / (4 * 256); ++it) {
                int idx = tid + it * 256;
                constexpr int NV = BN / 4;      // float4 per k-row
                int kk  = idx / NV;
                int nq  = (idx - kk * NV) * 4;
                float4 vv = *reinterpret_cast<const float4*>(
                    Bm + (long long)(k0 + kk) * ldb + n0 + nq);
                *reinterpret_cast<float4*>(&Bs[kk][nq]) = vv;
            }
        }
        __syncthreads();

        // ---- compute ----
#pragma unroll
        for (int kk = 0; kk < BK; ++kk) {
            float a[TM], b[TN];
#pragma unroll
            for (int i = 0; i < TM; i += 4) {
                float4 t = *reinterpret_cast<const float4*>(&As[kk][ty * TM + i]);
                a[i] = t.x; a[i + 1] = t.y; a[i + 2] = t.z; a[i + 3] = t.w;
            }
#pragma unroll
            for (int j = 0; j < TN; j += 4) {
                float4 t = *reinterpret_cast<const float4*>(&Bs[kk][tx * TN + j]);
                b[j] = t.x; b[j + 1] = t.y; b[j + 2] = t.z; b[j + 3] = t.w;
            }
#pragma unroll
            for (int i = 0; i < TM; ++i)
#pragma unroll
                for (int j = 0; j < TN; ++j)
                    acc[i][j] = fmaf(a[i], b[j], acc[i][j]);
        }
        __syncthreads();
    }

    // ---- epilogue ----
#pragma unroll
    for (int i = 0; i < TM; ++i) {
        int m = m0 + ty * TM + i;
#pragma unroll
        for (int j = 0; j < TN; ++j) {
            int n   = n0 + tx * TN + j;
            float v = acc[i][j] * alpha;
            if (BIAS) v += bias[n];
            if (RELU) v = fmaxf(v, 0.0f);
            C[(long long)m * ldc + n] = v;
        }
    }
}

// ---------------------------------------------------------------------------
// Repack per-head weights [H, D, HD] -> standard [D, H*HD]
// ---------------------------------------------------------------------------
__global__ void repack_kernel(const float* __restrict__ w, float* __restrict__ o)
{
    int idx = blockIdx.x * 256 + threadIdx.x;      // 0 .. D*D-1
    int h = idx >> 16;                              // / (D*HD = 65536)
    int r = idx & 65535;
    int k = r >> 6;
    int e = r & 63;
    o[k * (kH * kHD) + h * kHD + e] = w[idx];
}

// ---------------------------------------------------------------------------
// Row softmax over last dim (2048 cols), in place. One block per row.
// ---------------------------------------------------------------------------
__global__ __launch_bounds__(256)
void softmax_kernel(float* __restrict__ s)
{
    const long long row = blockIdx.x;
    float4* p = reinterpret_cast<float4*>(s) + row * (kS / 4);   // 512 float4
    const int tid = threadIdx.x;

    __shared__ float red[256];

    float mx = -1e30f;
#pragma unroll
    for (int it = 0; it < 2; ++it) {
        float4 v = p[tid + it * 256];
        mx = fmaxf(mx, fmaxf(fmaxf(v.x, v.y), fmaxf(v.z, v.w)));
    }
    red[tid] = mx;
    __syncthreads();
    for (int o = 128; o > 0; o >>= 1) {
        if (tid < o) red[tid] = fmaxf(red[tid], red[tid + o]);
        __syncthreads();
    }
    mx = red[0];
    __syncthreads();

    float sum = 0.0f;
#pragma unroll
    for (int it = 0; it < 2; ++it) {
        float4 v = p[tid + it * 256];
        v.x = expf(v.x - mx);
        v.y = expf(v.y - mx);
        v.z = expf(v.z - mx);
        v.w = expf(v.w - mx);
        p[tid + it * 256] = v;
        sum += v.x + v.y + v.z + v.w;
    }
    red[tid] = sum;
    __syncthreads();
    for (int o = 128; o > 0; o >>= 1) {
        if (tid < o) red[tid] += red[tid + o];
        __syncthreads();
    }
    float inv = 1.0f / red[0];
#pragma unroll
    for (int it = 0; it < 2; ++it) {
        float4 v = p[tid + it * 256];
        v.x *= inv; v.y *= inv; v.z *= inv; v.w *= inv;
        p[tid + it * 256] = v;
    }
}

// ---------------------------------------------------------------------------
// out = LayerNorm(x + d) * g + b, rows of length D=1024. One block per row,
// 256 threads, one float4 per thread.
// ---------------------------------------------------------------------------
__global__ __launch_bounds__(256)
void add_ln_kernel(const float* __restrict__ x, const float* __restrict__ d,
                   const float* __restrict__ g, const float* __restrict__ b,
                   float* __restrict__ out)
{
    const long long row = blockIdx.x;
    const int tid = threadIdx.x;
    const float4* x4 = reinterpret_cast<const float4*>(x) + row * (kD / 4);
    const float4* d4 = reinterpret_cast<const float4*>(d) + row * (kD / 4);
    const float4* g4 = reinterpret_cast<const float4*>(g);
    const float4* b4 = reinterpret_cast<const float4*>(b);
    float4* o4 = reinterpret_cast<float4*>(out) + row * (kD / 4);

    float4 xv = x4[tid];
    float4 dv = d4[tid];
    float4 v;
    v.x = xv.x + dv.x; v.y = xv.y + dv.y; v.z = xv.z + dv.z; v.w = xv.w + dv.w;

    float s  = v.x + v.y + v.z + v.w;
    float sq = v.x * v.x + v.y * v.y + v.z * v.z + v.w * v.w;

    __shared__ float rs[256];
    __shared__ float rq[256];
    rs[tid] = s;
    rq[tid] = sq;
    __syncthreads();
    for (int o = 128; o > 0; o >>= 1) {
        if (tid < o) { rs[tid] += rs[tid + o]; rq[tid] += rq[tid + o]; }
        __syncthreads();
    }
    const float mean = rs[0] * (1.0f / kD);
    const float var  = rq[0] * (1.0f / kD) - mean * mean;
    const float rstd = rsqrtf(var + kEps);

    float4 gv = g4[tid];
    float4 bv = b4[tid];
    float4 ov;
    ov.x = (v.x - mean) * rstd * gv.x + bv.x;
    ov.y = (v.y - mean) * rstd * gv.y + bv.y;
    ov.z = (v.z - mean) * rstd * gv.z + bv.z;
    ov.w = (v.w - mean) * rstd * gv.w + bv.w;
    o4[tid] = ov;
}

// ---------------------------------------------------------------------------
// kernel_launch
// ---------------------------------------------------------------------------
extern "C" void kernel_launch(void* const* d_in, const int* in_sizes, int n_in,
                              void* d_out, int out_size)
{
    (void)in_sizes; (void)n_in; (void)out_size;

    const float* X     = (const float*)d_in[0];
    const float* Wq    = (const float*)d_in[1];
    const float* bq    = (const float*)d_in[2];
    const float* Wk    = (const float*)d_in[3];
    const float* bk    = (const float*)d_in[4];
    const float* Wv    = (const float*)d_in[5];
    const float* bv    = (const float*)d_in[6];
    const float* Wo    = (const float*)d_in[7];
    const float* bo    = (const float*)d_in[8];
    const float* ln1_g = (const float*)d_in[9];
    const float* ln1_b = (const float*)d_in[10];
    const float* W1    = (const float*)d_in[11];
    const float* b1    = (const float*)d_in[12];
    const float* W2    = (const float*)d_in[13];
    const float* b2    = (const float*)d_in[14];
    const float* ln2_g = (const float*)d_in[15];
    const float* ln2_b = (const float*)d_in[16];
    float* out = (float*)d_out;

    float *wr, *q, *k, *v, *sc, *at, *pr, *y, *f1, *f2;
    cudaGetSymbolAddress((void**)&wr, g_wr);
    cudaGetSymbolAddress((void**)&q,  g_q);
    cudaGetSymbolAddress((void**)&k,  g_k);
    cudaGetSymbolAddress((void**)&v,  g_v);
    cudaGetSymbolAddress((void**)&sc, g_scores);
    cudaGetSymbolAddress((void**)&at, g_attn);
    cudaGetSymbolAddress((void**)&pr, g_proj);
    cudaGetSymbolAddress((void**)&y,  g_y);
    cudaGetSymbolAddress((void**)&f1, g_ff1);
    cudaGetSymbolAddress((void**)&f2, g_ff2);

    const long long WSZ = (long long)kD * kD;

    // 1) repack per-head QKV weights into [D, H*HD]
    repack_kernel<<<(kD * kD) / 256, 256>>>(Wq, wr + 0 * WSZ);
    repack_kernel<<<(kD * kD) / 256, 256>>>(Wk, wr + 1 * WSZ);
    repack_kernel<<<(kD * kD) / 256, 256>>>(Wv, wr + 2 * WSZ);

    // 2) Q/K/V projections: [4096,1024] x [1024,1024] + bias
    dim3 gQ(kD / 128, kM / 128, 1);
    sgemm_kernel<128, 128, 8, 8, false, false, true><<<gQ, 256>>>(
        X, wr + 0 * WSZ, bq, q, kM, kD, kD, kD, kD, kD,
        0, 0, 0, 0, 0, 0, 1, 1.0f);
    sgemm_kernel<128, 128, 8, 8, false, false, true><<<gQ, 256>>>(
        X, wr + 1 * WSZ, bk, k, kM, kD, kD, kD, kD, kD,
        0, 0, 0, 0, 0, 0, 1, 1.0f);
    sgemm_kernel<128, 128, 8, 8, false, false, true><<<gQ, 256>>>(
        X, wr + 2 * WSZ, bv, v, kM, kD, kD, kD, kD, kD,
        0, 0, 0, 0, 0, 0, 1, 1.0f);

    // 3) scores = (Q K^T) / sqrt(HD), batched over (b,h): NT GEMM
    dim3 gS(kS / 128, kS / 128, kB * kH);
    sgemm_kernel<128, 128, 8, 8, true, false, false><<<gS, 256>>>(
        q, k, nullptr, sc, kS, kS, kHD, kD, kD, kS,
        (long long)kS * kD, kHD,
        (long long)kS * kD, kHD,
        (long long)kH * kS * kS, (long long)kS * kS,
        kH, 0.125f);

    // 4) row softmax
    softmax_kernel<<<kB * kH * kS, 256>>>(sc);

    // 5) attn = P V, batched: NN GEMM with N = 64
    dim3 gA(1, kS / 128, kB * kH);
    sgemm_kernel<128, 64, 8, 4, false, false, false><<<gA, 256>>>(
        sc, v, nullptr, at, kS, kHD, kS, kS, kD, kD,
        (long long)kH * kS * kS, (long long)kS * kS,
        (long long)kS * kD, kHD,
        (long long)kS * kD, kHD,
        kH, 1.0f);

    // 6) output projection + bias
    sgemm_kernel<128, 128, 8, 8, false, false, true><<<gQ, 256>>>(
        at, Wo, bo, pr, kM, kD, kD, kD, kD, kD,
        0, 0, 0, 0, 0, 0, 1, 1.0f);

    // 7) y = LN1(X + proj)
    add_ln_kernel<<<kM, 256>>>(X, pr, ln1_g, ln1_b, y);

    // 8) ff1 = relu(y W1 + b1): [4096,1024] x [1024,4096]
    dim3 gF1(kDFF / 128, kM / 128, 1);
    sgemm_kernel<128, 128, 8, 8, false, true, true><<<gF1, 256>>>(
        y, W1, b1, f1, kM, kDFF, kD, kD, kDFF, kDFF,
        0, 0, 0, 0, 0, 0, 1, 1.0f);

    // 9) ff2 = ff1 W2 + b2: [4096,4096] x [4096,1024]
    dim3 gF2(kD / 128, kM / 128, 1);
    sgemm_kernel<128, 128, 8, 8, false, false, true><<<gF2, 256>>>(
        f1, W2, b2, f2, kM, kD, kDFF, kDFF, kD, kD,
        0, 0, 0, 0, 0, 0, 1, 1.0f);

    // 10) out = LN2(y + ff2)
    add_ln_kernel<<<kM, 256>>>(y, f2, ln2_g, ln2_b, out);
}

// round 2
// speedup vs baseline: 1.0010x; 1.0010x over previous
#include <cuda_runtime.h>

// ---------------------------------------------------------------------------
// Problem constants
// ---------------------------------------------------------------------------
namespace {
constexpr int kB   = 2;
constexpr int kS   = 2048;
constexpr int kD   = 1024;
constexpr int kH   = 16;
constexpr int kHD  = 64;
constexpr int kDFF = 4096;
constexpr int kM   = kB * kS;   // 4096 rows
constexpr float kEps = 1e-5f;
}

// ---------------------------------------------------------------------------
// Device scratch (static __device__ globals -- no allocation anywhere)
// ---------------------------------------------------------------------------
__device__ float g_wr[3][(size_t)kD * kD];                 // repacked Wq/Wk/Wv
__device__ float g_q[(size_t)kM * kD];
__device__ float g_k[(size_t)kM * kD];
__device__ float g_v[(size_t)kM * kD];
__device__ float g_scores[(size_t)kB * kH * kS * kS];      // 512 MB
__device__ float g_attn[(size_t)kM * kD];
__device__ float g_proj[(size_t)kM * kD];
__device__ float g_y[(size_t)kM * kD];
__device__ float g_ff1[(size_t)kM * kDFF];                 // 64 MB
__device__ float g_ff2[(size_t)kM * kD];

// ---------------------------------------------------------------------------
// Generic tiled SGEMM.
//   C[m][n] = alpha * sum_k A[m][k] * B[k][n]   (TRANSB=false, B is KxN)
//   C[m][n] = alpha * sum_k A[m][k] * B[n][k]   (TRANSB=true,  B is NxK)
// Optional bias[n] add and ReLU. Batched via blockIdx.z with split strides:
//   base += (z / bdiv) * s?1 + (z % bdiv) * s?2
// Requirements (guaranteed by call sites): M % BM == 0, N % BN == 0,
// K % 16 == 0, all pointers/leading dims 16B aligned.
// ---------------------------------------------------------------------------
template <int BM, int BN, int TM, int TN, bool TRANSB, bool RELU, bool BIAS>
__global__ __launch_bounds__(256)
void sgemm_kernel(const float* __restrict__ A, const float* __restrict__ Bm,
                  const float* __restrict__ bias, float* __restrict__ C,
                  int M, int N, int K, int lda, int ldb, int ldc,
                  long long sA1, long long sA2,
                  long long sB1, long long sB2,
                  long long sC1, long long sC2,
                  int bdiv, float alpha)
{
    constexpr int BK  = 16;
    constexpr int PAD = 4;
    __shared__ float As[BK][BM + PAD];
    __shared__ float Bs[BK][BN + PAD];

    const int z  = blockIdx.z;
    const int zb = z / bdiv;
    const int zh = z - zb * bdiv;
    A  += zb * sA1 + zh * sA2;
    Bm += zb * sB1 + zh * sB2;
    C  += zb * sC1 + zh * sC2;

    const int m0  = blockIdx.y * BM;
    const int n0  = blockIdx.x * BN;
    const int tid = threadIdx.x;
    const int tx  = tid & 15;       // 16 columns of threads
    const int ty  = tid >> 4;       // 16 rows of threads

    float acc[TM][TN];
#pragma unroll
    for (int i = 0; i < TM; ++i)
#pragma unroll
        for (int j = 0; j < TN; ++j) acc[i][j] = 0.0f;

    for (int k0 = 0; k0 < K; k0 += BK) {
        // ---- load A tile: BM x BK (k contiguous in gmem) ----
#pragma unroll
        for (int it = 0; it < (BM * BK) / (4 * 256); ++it) {
            int idx = tid + it * 256;
            int m   = idx >> 2;            // 4 float4 per row (BK=16)
            int kq  = (idx & 3) * 4;
            float4 vv = *reinterpret_cast<const float4*>(
                A + (long long)(m0 + m) * lda + k0 + kq);
            As[kq + 0][m] = vv.x;
            As[kq + 1][m] = vv.y;
            As[kq + 2][m] = vv.z;
            As[kq + 3][m] = vv.w;
        }
        // ---- load B tile ----
        if (TRANSB) {
#pragma unroll
            for (int it = 0; it < (BN * BK) / (4 * 256); ++it) {
                int idx = tid + it * 256;
                int n   = idx >> 2;
                int kq  = (idx & 3) * 4;
                float4 vv = *reinterpret_cast<const float4*>(
                    Bm + (long long)(n0 + n) * ldb + k0 + kq);
                Bs[kq + 0][n] = vv.x;
                Bs[kq + 1][n] = vv.y;
                Bs[kq + 2][n] = vv.z;
                Bs[kq + 3][n] = vv.w;
            }
        } else {
#pragma unroll
            for (int it = 0; it < (BN * BK) / (4 * 256); ++it) {
                int idx = tid + it * 256;
                constexpr int NV = BN / 4;      // float4 per k-row
                int kk  = idx / NV;
                int nq  = (idx - kk * NV) * 4;
                float4 vv = *reinterpret_cast<const float4*>(
                    Bm + (long long)(k0 + kk) * ldb + n0 + nq);
                *reinterpret_cast<float4*>(&Bs[kk][nq]) = vv;
            }
        }
        __syncthreads();

        // ---- compute ----
#pragma unroll
        for (int kk = 0; kk < BK; ++kk) {
            float a[TM], b[TN];
#pragma unroll
            for (int i = 0; i < TM; i += 4) {
                float4 t = *reinterpret_cast<const float4*>(&As[kk][ty * TM + i]);
                a[i] = t.x; a[i + 1] = t.y; a[i + 2] = t.z; a[i + 3] = t.w;
            }
#pragma unroll
            for (int j = 0; j < TN; j += 4) {
                float4 t = *reinterpret_cast<const float4*>(&Bs[kk][tx * TN + j]);
                b[j] = t.x; b[j + 1] = t.y; b[j + 2] = t.z; b[j + 3] = t.w;
            }
#pragma unroll
            for (int i = 0; i < TM; ++i)
#pragma unroll
                for (int j = 0; j < TN; ++j)
                    acc[i][j] = fmaf(a[i], b[j], acc[i][j]);
        }
        __syncthreads();
    }

    // ---- epilogue ----
#pragma unroll
    for (int i = 0; i < TM; ++i) {
        int m = m0 + ty * TM + i;
#pragma unroll
        for (int j = 0; j < TN; ++j) {
            int n   = n0 + tx * TN + j;
            float v = acc[i][j] * alpha;
            if (BIAS) v += bias[n];
            if (RELU) v = fmaxf(v, 0.0f);
            C[(long long)m * ldc + n] = v;
        }
    }
}

// ---------------------------------------------------------------------------
// Repack per-head weights [H, D, HD] -> standard [D, H*HD]
// ---------------------------------------------------------------------------
__global__ void repack_kernel(const float* __restrict__ w, float* __restrict__ o)
{
    int idx = blockIdx.x * 256 + threadIdx.x;      // 0 .. D*D-1
    int h = idx >> 16;                              // / (D*HD = 65536)
    int r = idx & 65535;
    int k = r >> 6;
    int e = r & 63;
    o[k * (kH * kHD) + h * kHD + e] = w[idx];
}

// ---------------------------------------------------------------------------
// Row softmax over last dim (2048 cols), in place. One block per row.
// ---------------------------------------------------------------------------
__global__ __launch_bounds__(256)
void softmax_kernel(float* __restrict__ s)
{
    const long long row = blockIdx.x;
    float4* p = reinterpret_cast<float4*>(s) + row * (kS / 4);   // 512 float4
    const int tid = threadIdx.x;

    __shared__ float red[256];

    float mx = -1e30f;
#pragma unroll
    for (int it = 0; it < 2; ++it) {
        float4 v = p[tid + it * 256];
        mx = fmaxf(mx, fmaxf(fmaxf(v.x, v.y), fmaxf(v.z, v.w)));
    }
    red[tid] = mx;
    __syncthreads();
    for (int o = 128; o > 0; o >>= 1) {
        if (tid < o) red[tid] = fmaxf(red[tid], red[tid + o]);
        __syncthreads();
    }
    mx = red[0];
    __syncthreads();

    float sum = 0.0f;
#pragma unroll
    for (int it = 0; it < 2; ++it) {
        float4 v = p[tid + it * 256];
        v.x = expf(v.x - mx);
        v.y = expf(v.y - mx);
        v.z = expf(v.z - mx);
        v.w = expf(v.w - mx);
        p[tid + it * 256] = v;
        sum += v.x + v.y + v.z + v.w;
    }
    red[tid] = sum;
    __syncthreads();
    for (int o = 128; o > 0; o >>= 1) {
        if (tid < o) red[tid] += red[tid + o];
        __syncthreads();
    }
    float inv = 1.0f / red[0];
#pragma unroll
    for (int it = 0; it < 2; ++it) {
        float4 v = p[tid + it * 256];
        v.x *= inv; v.y *= inv; v.z *= inv; v.w *= inv;
        p[tid + it * 256] = v;
    }
}

// ---------------------------------------------------------------------------
// out = LayerNorm(x + d) * g + b, rows of length D=1024. One block per row,
// 256 threads, one float4 per thread.
// ---------------------------------------------------------------------------
__global__ __launch_bounds__(256)
void add_ln_kernel(const float* __restrict__ x, const float* __restrict__ d,
                   const float* __restrict__ g, const float* __restrict__ b,
                   float* __restrict__ out)
{
    const long long row = blockIdx.x;
    const int tid = threadIdx.x;
    const float4* x4 = reinterpret_cast<const float4*>(x) + row * (kD / 4);
    const float4* d4 = reinterpret_cast<const float4*>(d) + row * (kD / 4);
    const float4* g4 = reinterpret_cast<const float4*>(g);
    const float4* b4 = reinterpret_cast<const float4*>(b);
    float4* o4 = reinterpret_cast<float4*>(out) + row * (kD / 4);

    float4 xv = x4[tid];
    float4 dv = d4[tid];
    float4 v;
    v.x = xv.x + dv.x; v.y = xv.y + dv.y; v.z = xv.z + dv.z; v.w = xv.w + dv.w;

    float s  = v.x + v.y + v.z + v.w;
    float sq = v.x * v.x + v.y * v.y + v.z * v.z + v.w * v.w;

    __shared__ float rs[256];
    __shared__ float rq[256];
    rs[tid] = s;
    rq[tid] = sq;
    __syncthreads();
    for (int o = 128; o > 0; o >>= 1) {
        if (tid < o) { rs[tid] += rs[tid + o]; rq[tid] += rq[tid + o]; }
        __syncthreads();
    }
    const float mean = rs[0] * (1.0f / kD);
    const float var  = rq[0] * (1.0f / kD) - mean * mean;
    const float rstd = rsqrtf(var + kEps);

    float4 gv = g4[tid];
    float4 bv = b4[tid];
    float4 ov;
    ov.x = (v.x - mean) * rstd * gv.x + bv.x;
    ov.y = (v.y - mean) * rstd * gv.y + bv.y;
    ov.z = (v.z - mean) * rstd * gv.z + bv.z;
    ov.w = (v.w - mean) * rstd * gv.w + bv.w;
    o4[tid] = ov;
}

// ---------------------------------------------------------------------------
// kernel_launch
// ---------------------------------------------------------------------------
extern "C" void kernel_launch(void* const* d_in, const int* in_sizes, int n_in,
                              void* d_out, int out_size)
{
    (void)in_sizes; (void)n_in; (void)out_size;

    const float* X     = (const float*)d_in[0];
    const float* Wq    = (const float*)d_in[1];
    const float* bq    = (const float*)d_in[2];
    const float* Wk    = (const float*)d_in[3];
    const float* bk    = (const float*)d_in[4];
    const float* Wv    = (const float*)d_in[5];
    const float* bv    = (const float*)d_in[6];
    const float* Wo    = (const float*)d_in[7];
    const float* bo    = (const float*)d_in[8];
    const float* ln1_g = (const float*)d_in[9];
    const float* ln1_b = (const float*)d_in[10];
    const float* W1    = (const float*)d_in[11];
    const float* b1    = (const float*)d_in[12];
    const float* W2    = (const float*)d_in[13];
    const float* b2    = (const float*)d_in[14];
    const float* ln2_g = (const float*)d_in[15];
    const float* ln2_b = (const float*)d_in[16];
    float* out = (float*)d_out;

    float *wr, *q, *k, *v, *sc, *at, *pr, *y, *f1, *f2;
    cudaGetSymbolAddress((void**)&wr, g_wr);
    cudaGetSymbolAddress((void**)&q,  g_q);
    cudaGetSymbolAddress((void**)&k,  g_k);
    cudaGetSymbolAddress((void**)&v,  g_v);
    cudaGetSymbolAddress((void**)&sc, g_scores);
    cudaGetSymbolAddress((void**)&at, g_attn);
    cudaGetSymbolAddress((void**)&pr, g_proj);
    cudaGetSymbolAddress((void**)&y,  g_y);
    cudaGetSymbolAddress((void**)&f1, g_ff1);
    cudaGetSymbolAddress((void**)&f2, g_ff2);

    const long long WSZ = (long long)kD * kD;

    // 1) repack per-head QKV weights into [D, H*HD]
    repack_kernel<<<(kD * kD) / 256, 256>>>(Wq, wr + 0 * WSZ);
    repack_kernel<<<(kD * kD) / 256, 256>>>(Wk, wr + 1 * WSZ);
    repack_kernel<<<(kD * kD) / 256, 256>>>(Wv, wr + 2 * WSZ);

    // 2) Q/K/V projections: [4096,1024] x [1024,1024] + bias
    dim3 gQ(kD / 128, kM / 128, 1);
    sgemm_kernel<128, 128, 8, 8, false, false, true><<<gQ, 256>>>(
        X, wr + 0 * WSZ, bq, q, kM, kD, kD, kD, kD, kD,
        0, 0, 0, 0, 0, 0, 1, 1.0f);
    sgemm_kernel<128, 128, 8, 8, false, false, true><<<gQ, 256>>>(
        X, wr + 1 * WSZ, bk, k, kM, kD, kD, kD, kD, kD,
        0, 0, 0, 0, 0, 0, 1, 1.0f);
    sgemm_kernel<128, 128, 8, 8, false, false, true><<<gQ, 256>>>(
        X, wr + 2 * WSZ, bv, v, kM, kD, kD, kD, kD, kD,
        0, 0, 0, 0, 0, 0, 1, 1.0f);

    // 3) scores = (Q K^T) / sqrt(HD), batched over (b,h): NT GEMM
    dim3 gS(kS / 128, kS / 128, kB * kH);
    sgemm_kernel<128, 128, 8, 8, true, false, false><<<gS, 256>>>(
        q, k, nullptr, sc, kS, kS, kHD, kD, kD, kS,
        (long long)kS * kD, kHD,
        (long long)kS * kD, kHD,
        (long long)kH * kS * kS, (long long)kS * kS,
        kH, 0.125f);

    // 4) row softmax
    softmax_kernel<<<kB * kH * kS, 256>>>(sc);

    // 5) attn = P V, batched: NN GEMM with N = 64
    dim3 gA(1, kS / 128, kB * kH);
    sgemm_kernel<128, 64, 8, 4, false, false, false><<<gA, 256>>>(
        sc, v, nullptr, at, kS, kHD, kS, kS, kD, kD,
        (long long)kH * kS * kS, (long long)kS * kS,
        (long long)kS * kD, kHD,
        (long long)kS * kD, kHD,
        kH, 1.0f);

    // 6) output projection + bias
    sgemm_kernel<128, 128, 8, 8, false, false, true><<<gQ, 256>>>(
        at, Wo, bo, pr, kM, kD, kD, kD, kD, kD,
        0, 0, 0, 0, 0, 0, 1, 1.0f);

    // 7) y = LN1(X + proj)
    add_ln_kernel<<<kM, 256>>>(X, pr, ln1_g, ln1_b, y);

    // 8) ff1 = relu(y W1 + b1): [4096,1024] x [1024,4096]
    dim3 gF1(kDFF / 128, kM / 128, 1);
    sgemm_kernel<128, 128, 8, 8, false, true, true><<<gF1, 256>>>(
        y, W1, b1, f1, kM, kDFF, kD, kD, kDFF, kDFF,
        0, 0, 0, 0, 0, 0, 1, 1.0f);

    // 9) ff2 = ff1 W2 + b2: [4096,4096] x [4096,1024]
    dim3 gF2(kD / 128, kM / 128, 1);
    sgemm_kernel<128, 128, 8, 8, false, false, true><<<gF2, 256>>>(
        f1, W2, b2, f2, kM, kD, kDFF, kDFF, kD, kD,
        0, 0, 0, 0, 0, 0, 1, 1.0f);

    // 10) out = LN2(y + ff2)
    add_ln_kernel<<<kM, 256>>>(y, f2, ln2_g, ln2_b, out);
}

// round 6
// speedup vs baseline: 2.6176x; 2.6150x over previous
#include <cuda_runtime.h>
#include <cuda_bf16.h>
#include <cstdint>

using bf16 = __nv_bfloat16;

constexpr int kB = 2, kS = 2048, kD = 1024, kH = 16, kHD = 64, kDFF = 4096;
constexpr int kM = kB * kS;
constexpr float kEps = 1e-5f;

constexpr long long WQKV = 0;            // [3072][1024]
constexpr long long WO   = 3145728;      // [1024][1024]
constexpr long long W1O  = 4194304;      // [4096][1024]
constexpr long long W2O  = 8388608;      // [1024][4096]
constexpr long long WTOT = 12582912;

__device__ bf16  g_wh[WTOT], g_wl[WTOT];
__device__ float g_bias[3072];
__device__ bf16  g_xh[4194304], g_xl[4194304];
__device__ bf16  g_qh[12582912], g_ql[12582912];     // fused QKV out [4096][3072]
__device__ float g_sc[134217728];                    // [B*H][2048][2048]
__device__ bf16  g_ph[134217728], g_pl[134217728];
__device__ bf16  g_vth[4194304], g_vtl[4194304];     // V^T [B*H][64][2048]
__device__ bf16  g_ah[4194304], g_al[4194304];       // attn out [4096][1024]
__device__ float g_pr[4194304];
__device__ float g_y[4194304];
__device__ bf16  g_yh[4194304], g_yl[4194304];
__device__ bf16  g_f1h[16777216], g_f1l[16777216];   // [4096][4096]
__device__ float g_f2[4194304];

// ---------------- helpers ----------------
__device__ __forceinline__ uint32_t smem_u32(const void* p) {
    uint32_t a;
    asm("{ .reg .u64 t; cvta.to.shared.u64 t, %1; cvt.u32.u64 %0, t; }" : "=r"(a) : "l"(p));
    return a;
}
__device__ __forceinline__ void cp16(uint32_t s, const void* g) {
    asm volatile("cp.async.cg.shared.global [%0], [%1], 16;" :: "r"(s), "l"(g));
}
#define CP_COMMIT() asm volatile("cp.async.commit_group;" ::: "memory")
#define CP_WAIT(n)  asm volatile("cp.async.wait_group %0;" :: "n"(n) : "memory")
__device__ __forceinline__ uint32_t swz(uint32_t o) { return o ^ ((o >> 3) & 0x70); }

__device__ __forceinline__ void ldm4(uint32_t* r, uint32_t a) {
    asm volatile("ldmatrix.sync.aligned.m8n8.x4.shared.b16 {%0,%1,%2,%3}, [%4];"
                 : "=r"(r[0]), "=r"(r[1]), "=r"(r[2]), "=r"(r[3]) : "r"(a));
}
__device__ __forceinline__ void ldm2(uint32_t* r, uint32_t a) {
    asm volatile("ldmatrix.sync.aligned.m8n8.x2.shared.b16 {%0,%1}, [%2];"
                 : "=r"(r[0]), "=r"(r[1]) : "r"(a));
}
__device__ __forceinline__ void mma16816(float* c, const uint32_t* a, const uint32_t* b) {
    asm volatile("mma.sync.aligned.m16n8k16.row.col.f32.bf16.bf16.f32 "
                 "{%0,%1,%2,%3}, {%4,%5,%6,%7}, {%8,%9}, {%0,%1,%2,%3};"
                 : "+f"(c[0]), "+f"(c[1]), "+f"(c[2]), "+f"(c[3])
                 : "r"(a[0]), "r"(a[1]), "r"(a[2]), "r"(a[3]), "r"(b[0]), "r"(b[1]));
}
__device__ __forceinline__ uint32_t packhl(float a, float b, bool hi) {
    __nv_bfloat162 t;
    bf16 ha = __float2bfloat16(a), hb = __float2bfloat16(b);
    if (hi) { t.x = ha; t.y = hb; }
    else { t.x = __float2bfloat16(a - __bfloat162float(ha)); t.y = __float2bfloat16(b - __bfloat162float(hb)); }
    return *reinterpret_cast<uint32_t*>(&t);
}

// ---------------------------------------------------------------------------
// HMMA split-bf16 GEMM: C[m][n] = alpha*sum_k A[m][k]*B[n][k] (+bias,relu)
// 3-term: Ah*Bh + Ah*Bl + Al*Bh.  BM=128, BK=64, SW128-swizzled smem,
// cp.async double buffer, ldmatrix + mma.sync.m16n8k16.
// BN=128 -> 256 thr (8 warps, 2x4), BN=64 -> 128 thr (4 warps, 2x2).
// ---------------------------------------------------------------------------
template <int BN, bool BIAS, bool RELU, bool WF32>
__global__ __launch_bounds__(BN == 128 ? 256 : 128)
void hmma_gemm(const bf16* __restrict__ Ah, const bf16* __restrict__ Al,
               const bf16* __restrict__ Bh, const bf16* __restrict__ Bl,
               const float* __restrict__ bias,
               float* __restrict__ Cf, bf16* __restrict__ Ch, bf16* __restrict__ Cl,
               int K, int lda, int ldb, int ldc,
               long long sA1, long long sA2, long long sB1, long long sB2,
               long long sC1, long long sC2, int bdiv, float alpha)
{
    constexpr int THREADS = (BN == 128) ? 256 : 128;
    constexpr int WN = (BN == 128) ? 4 : 2;           // warps along n
    constexpr int AST = 128 * 128;                    // bytes, one A subtile
    constexpr int BST = BN * 128;
    constexpr int STAGE = 2 * AST + 2 * BST;

    extern __shared__ char smem[];
    const uint32_t st0 = (smem_u32(smem) + 127u) & ~127u;

    const int tid = threadIdx.x, wid = tid >> 5, lid = tid & 31;
    const int z = blockIdx.z, zb = z / bdiv, zh = z - zb * bdiv;
    Ah += zb * sA1 + zh * sA2;  Al += zb * sA1 + zh * sA2;
    Bh += zb * sB1 + zh * sB2;  Bl += zb * sB1 + zh * sB2;
    const long long cOff = zb * sC1 + zh * sC2;
    const int m0 = blockIdx.y * 128, n0 = blockIdx.x * BN;
    const int wm0 = (wid / WN) * 64, wn0 = (wid % WN) * 32;

    const int nk = K >> 6;

    auto load = [&](int s) {
        uint32_t aH = st0 + (s & 1) * STAGE, aL = aH + AST, bH = aL + AST, bL = bH + BST;
        const int k0 = s << 6;
#pragma unroll
        for (int c = tid; c < 1024; c += THREADS) {
            int r = c >> 3, cj = c & 7;
            uint32_t so = swz((uint32_t)((r << 7) + (cj << 4)));
            long long go = (long long)(m0 + r) * lda + k0 + (cj << 3);
            cp16(aH + so, Ah + go);
            cp16(aL + so, Al + go);
        }
#pragma unroll
        for (int c = tid; c < BN * 8; c += THREADS) {
            int r = c >> 3, cj = c & 7;
            uint32_t so = swz((uint32_t)((r << 7) + (cj << 4)));
            long long go = (long long)(n0 + r) * ldb + k0 + (cj << 3);
            cp16(bH + so, Bh + go);
            cp16(bL + so, Bl + go);
        }
    };

    float acc[4][4][4];
#pragma unroll
    for (int i = 0; i < 4; ++i)
#pragma unroll
        for (int j = 0; j < 4; ++j)
#pragma unroll
            for (int q = 0; q < 4; ++q) acc[i][j][q] = 0.0f;

    load(0); CP_COMMIT();

    for (int it = 0; it < nk; ++it) {
        if (it + 1 < nk) { load(it + 1); CP_COMMIT(); CP_WAIT(1); }
        else             { CP_WAIT(0); }
        __syncthreads();

        uint32_t aH = st0 + (it & 1) * STAGE, aL = aH + AST, bH = aL + AST, bL = bH + BST;
#pragma unroll
        for (int k16 = 0; k16 < 4; ++k16) {
            uint32_t ah[4][4], al[4][4], bh[4][2], bl[4][2];
#pragma unroll
            for (int mi = 0; mi < 4; ++mi) {
                uint32_t byte = (uint32_t)((wm0 + mi * 16 + (lid & 15)) << 7)
                              + (uint32_t)((k16 * 2 + (lid >> 4)) << 4);
                uint32_t so = swz(byte);
                ldm4(ah[mi], aH + so);
                ldm4(al[mi], aL + so);
            }
#pragma unroll
            for (int ni = 0; ni < 4; ++ni) {
                uint32_t byte = (uint32_t)((wn0 + ni * 8 + (lid & 7)) << 7)
                              + (uint32_t)((k16 * 2 + ((lid >> 3) & 1)) << 4);
                uint32_t so = swz(byte);
                ldm2(bh[ni], bH + so);
                ldm2(bl[ni], bL + so);
            }
#pragma unroll
            for (int mi = 0; mi < 4; ++mi)
#pragma unroll
                for (int ni = 0; ni < 4; ++ni) mma16816(acc[mi][ni], ah[mi], bh[ni]);
#pragma unroll
            for (int mi = 0; mi < 4; ++mi)
#pragma unroll
                for (int ni = 0; ni < 4; ++ni) mma16816(acc[mi][ni], ah[mi], bl[ni]);
#pragma unroll
            for (int mi = 0; mi < 4; ++mi)
#pragma unroll
                for (int ni = 0; ni < 4; ++ni) mma16816(acc[mi][ni], al[mi], bh[ni]);
        }
        __syncthreads();
    }

    // ---- epilogue ----
#pragma unroll
    for (int mi = 0; mi < 4; ++mi) {
        const int gm = m0 + wm0 + mi * 16 + (lid >> 2);
#pragma unroll
        for (int ni = 0; ni < 4; ++ni) {
            const int gn = n0 + wn0 + ni * 8 + ((lid & 3) << 1);
            float v0 = acc[mi][ni][0] * alpha, v1 = acc[mi][ni][1] * alpha;
            float v2 = acc[mi][ni][2] * alpha, v3 = acc[mi][ni][3] * alpha;
            if (BIAS) {
                float b0 = bias[gn], b1 = bias[gn + 1];
                v0 += b0; v1 += b1; v2 += b0; v3 += b1;
            }
            if (RELU) {
                v0 = fmaxf(v0, 0.0f); v1 = fmaxf(v1, 0.0f);
                v2 = fmaxf(v2, 0.0f); v3 = fmaxf(v3, 0.0f);
            }
            if (WF32) {
                float2* p0 = reinterpret_cast<float2*>(Cf + cOff + (long long)gm * ldc + gn);
                float2* p1 = reinterpret_cast<float2*>(Cf + cOff + (long long)(gm + 8) * ldc + gn);
                *p0 = make_float2(v0, v1);
                *p1 = make_float2(v2, v3);
            } else {
                *reinterpret_cast<uint32_t*>(Ch + cOff + (long long)gm * ldc + gn)       = packhl(v0, v1, true);
                *reinterpret_cast<uint32_t*>(Cl + cOff + (long long)gm * ldc + gn)       = packhl(v0, v1, false);
                *reinterpret_cast<uint32_t*>(Ch + cOff + (long long)(gm + 8) * ldc + gn) = packhl(v2, v3, true);
                *reinterpret_cast<uint32_t*>(Cl + cOff + (long long)(gm + 8) * ldc + gn) = packhl(v2, v3, false);
            }
        }
    }
}

// ---------------- prep kernels ----------------
__global__ __launch_bounds__(256)
void tsplit_w(const float* __restrict__ in, bf16* __restrict__ oh, bf16* __restrict__ ol,
              int ldi, int ldo, long long ibs, long long obs)
{
    __shared__ float t[32][33];
    const int z = blockIdx.z;
    const float* ip = in + z * ibs;
    bf16 *ohp = oh + z * obs, *olp = ol + z * obs;
    const int r0 = blockIdx.x * 32, c0 = blockIdx.y * 32;
    const int tx = threadIdx.x & 31, ty = threadIdx.x >> 5;
#pragma unroll
    for (int j = 0; j < 32; j += 8)
        t[ty + j][tx] = ip[(long long)(r0 + ty + j) * ldi + c0 + tx];
    __syncthreads();
#pragma unroll
    for (int j = 0; j < 32; j += 8) {
        float v = t[tx][ty + j];
        bf16 h = __float2bfloat16(v);
        long long o = (long long)(c0 + ty + j) * ldo + r0 + tx;
        ohp[o] = h;
        olp[o] = __float2bfloat16(v - __bfloat162float(h));
    }
}

__global__ __launch_bounds__(256)
void vtrans(const bf16* __restrict__ vh, const bf16* __restrict__ vl,
            bf16* __restrict__ oh, bf16* __restrict__ ol)
{
    __shared__ bf16 th[32][33], tl[32][33];
    const int z = blockIdx.z;
    const long long ib = (long long)(z >> 4) * 2048 * 3072 + 2048 + (z & 15) * 64;
    const long long ob = (long long)z * 64 * 2048;
    const int t0 = blockIdx.x * 32, e0 = blockIdx.y * 32;
    const int tx = threadIdx.x & 31, ty = threadIdx.x >> 5;
#pragma unroll
    for (int j = 0; j < 32; j += 8) {
        long long idx = ib + (long long)(t0 + ty + j) * 3072 + e0 + tx;
        th[ty + j][tx] = vh[idx];
        tl[ty + j][tx] = vl[idx];
    }
    __syncthreads();
#pragma unroll
    for (int j = 0; j < 32; j += 8) {
        long long o = ob + (long long)(e0 + ty + j) * 2048 + t0 + tx;
        oh[o] = th[tx][ty + j];
        ol[o] = tl[tx][ty + j];
    }
}

__global__ void biaspack(const float* q, const float* k, const float* v, float* o)
{
    int i = blockIdx.x * 256 + threadIdx.x;
    if (i < 1024) o[i] = q[i];
    else if (i < 2048) o[i] = k[i - 1024];
    else if (i < 3072) o[i] = v[i - 2048];
}

__global__ __launch_bounds__(256)
void xsplit(const float* __restrict__ in, bf16* __restrict__ oh, bf16* __restrict__ ol, int n4)
{
    int i = blockIdx.x * 256 + threadIdx.x;
    if (i >= n4) return;
    float4 v = reinterpret_cast<const float4*>(in)[i];
    uint2 uh = { packhl(v.x, v.y, true),  packhl(v.z, v.w, true)  };
    uint2 ul = { packhl(v.x, v.y, false), packhl(v.z, v.w, false) };
    reinterpret_cast<uint2*>(oh)[i] = uh;
    reinterpret_cast<uint2*>(ol)[i] = ul;
}

__global__ __launch_bounds__(256)
void softmax_hl(const float* __restrict__ s, bf16* __restrict__ oh, bf16* __restrict__ ol)
{
    const long long row = blockIdx.x;
    const float4* p = reinterpret_cast<const float4*>(s) + row * 512;
    const int tid = threadIdx.x;
    __shared__ float red[256];

    float4 a = p[tid], b2 = p[tid + 256];
    float mx = fmaxf(fmaxf(fmaxf(a.x, a.y), fmaxf(a.z, a.w)),
                     fmaxf(fmaxf(b2.x, b2.y), fmaxf(b2.z, b2.w)));
    red[tid] = mx; __syncthreads();
    for (int o = 128; o > 0; o >>= 1) { if (tid < o) red[tid] = fmaxf(red[tid], red[tid + o]); __syncthreads(); }
    mx = red[0]; __syncthreads();

    a.x = __expf(a.x - mx); a.y = __expf(a.y - mx); a.z = __expf(a.z - mx); a.w = __expf(a.w - mx);
    b2.x = __expf(b2.x - mx); b2.y = __expf(b2.y - mx); b2.z = __expf(b2.z - mx); b2.w = __expf(b2.w - mx);
    red[tid] = a.x + a.y + a.z + a.w + b2.x + b2.y + b2.z + b2.w; __syncthreads();
    for (int o = 128; o > 0; o >>= 1) { if (tid < o) red[tid] += red[tid + o]; __syncthreads(); }
    float inv = 1.0f / red[0];
    a.x *= inv; a.y *= inv; a.z *= inv; a.w *= inv;
    b2.x *= inv; b2.y *= inv; b2.z *= inv; b2.w *= inv;

    uint2* dh = reinterpret_cast<uint2*>(oh) + row * 512;
    uint2* dl = reinterpret_cast<uint2*>(ol) + row * 512;
    dh[tid]       = { packhl(a.x, a.y, true),  packhl(a.z, a.w, true)  };
    dl[tid]       = { packhl(a.x, a.y, false), packhl(a.z, a.w, false) };
    dh[tid + 256] = { packhl(b2.x, b2.y, true),  packhl(b2.z, b2.w, true)  };
    dl[tid + 256] = { packhl(b2.x, b2.y, false), packhl(b2.z, b2.w, false) };
}

template <bool SPLIT>
__global__ __launch_bounds__(256)
void add_ln(const float* __restrict__ x, const float* __restrict__ d,
            const float* __restrict__ g, const float* __restrict__ b,
            float* __restrict__ out, bf16* __restrict__ oh, bf16* __restrict__ ol)
{
    const long long row = blockIdx.x;
    const int tid = threadIdx.x;
    const float4* x4 = reinterpret_cast<const float4*>(x) + row * 256;
    const float4* d4 = reinterpret_cast<const float4*>(d) + row * 256;
    float4 xv = x4[tid], dv = d4[tid], v;
    v.x = xv.x + dv.x; v.y = xv.y + dv.y; v.z = xv.z + dv.z; v.w = xv.w + dv.w;

    __shared__ float rs[256], rq[256];
    rs[tid] = v.x + v.y + v.z + v.w;
    rq[tid] = v.x * v.x + v.y * v.y + v.z * v.z + v.w * v.w;
    __syncthreads();
    for (int o = 128; o > 0; o >>= 1) {
        if (tid < o) { rs[tid] += rs[tid + o]; rq[tid] += rq[tid + o]; }
        __syncthreads();
    }
    const float mean = rs[0] * (1.0f / kD);
    const float rstd = rsqrtf(rq[0] * (1.0f / kD) - mean * mean + kEps);

    float4 gv = reinterpret_cast<const float4*>(g)[tid];
    float4 bv = reinterpret_cast<const float4*>(b)[tid];
    float4 ov;
    ov.x = (v.x - mean) * rstd * gv.x + bv.x;
    ov.y = (v.y - mean) * rstd * gv.y + bv.y;
    ov.z = (v.z - mean) * rstd * gv.z + bv.z;
    ov.w = (v.w - mean) * rstd * gv.w + bv.w;
    reinterpret_cast<float4*>(out)[row * 256 + tid] = ov;
    if (SPLIT) {
        uint2 uh = { packhl(ov.x, ov.y, true),  packhl(ov.z, ov.w, true)  };
        uint2 ul = { packhl(ov.x, ov.y, false), packhl(ov.z, ov.w, false) };
        reinterpret_cast<uint2*>(oh)[row * 256 + tid] = uh;
        reinterpret_cast<uint2*>(ol)[row * 256 + tid] = ul;
    }
}

// ---------------------------------------------------------------------------
extern "C" void kernel_launch(void* const* d_in, const int* in_sizes, int n_in,
                              void* d_out, int out_size)
{
    (void)in_sizes; (void)n_in; (void)out_size;
    const float* X  = (const float*)d_in[0];
    const float* Wq = (const float*)d_in[1];  const float* bq = (const float*)d_in[2];
    const float* Wk = (const float*)d_in[3];  const float* bk = (const float*)d_in[4];
    const float* Wv = (const float*)d_in[5];  const float* bv = (const float*)d_in[6];
    const float* Wo = (const float*)d_in[7];  const float* bo = (const float*)d_in[8];
    const float* l1g = (const float*)d_in[9]; const float* l1b = (const float*)d_in[10];
    const float* W1 = (const float*)d_in[11]; const float* b1 = (const float*)d_in[12];
    const float* W2 = (const float*)d_in[13]; const float* b2 = (const float*)d_in[14];
    const float* l2g = (const float*)d_in[15]; const float* l2b = (const float*)d_in[16];
    float* out = (float*)d_out;

    bf16 *wh, *wl, *xh, *xl, *qh, *ql, *ph, *pl, *vth, *vtl, *ah, *al, *yh, *yl, *f1h, *f1l;
    float *bias, *sc, *pr, *y, *f2;
    cudaGetSymbolAddress((void**)&wh, g_wh);   cudaGetSymbolAddress((void**)&wl, g_wl);
    cudaGetSymbolAddress((void**)&bias, g_bias);
    cudaGetSymbolAddress((void**)&xh, g_xh);   cudaGetSymbolAddress((void**)&xl, g_xl);
    cudaGetSymbolAddress((void**)&qh, g_qh);   cudaGetSymbolAddress((void**)&ql, g_ql);
    cudaGetSymbolAddress((void**)&sc, g_sc);
    cudaGetSymbolAddress((void**)&ph, g_ph);   cudaGetSymbolAddress((void**)&pl, g_pl);
    cudaGetSymbolAddress((void**)&vth, g_vth); cudaGetSymbolAddress((void**)&vtl, g_vtl);
    cudaGetSymbolAddress((void**)&ah, g_ah);   cudaGetSymbolAddress((void**)&al, g_al);
    cudaGetSymbolAddress((void**)&pr, g_pr);   cudaGetSymbolAddress((void**)&y, g_y);
    cudaGetSymbolAddress((void**)&yh, g_yh);   cudaGetSymbolAddress((void**)&yl, g_yl);
    cudaGetSymbolAddress((void**)&f1h, g_f1h); cudaGetSymbolAddress((void**)&f1l, g_f1l);
    cudaGetSymbolAddress((void**)&f2, g_f2);

    constexpr int SM128 = 2 * (2 * 16384 + 2 * 16384) + 128;   // 131200
    constexpr int SM64  = 2 * (2 * 16384 + 2 * 8192) + 128;    //  98432
    cudaFuncSetAttribute((const void*)hmma_gemm<128, true,  false, false>, cudaFuncAttributeMaxDynamicSharedMemorySize, SM128);
    cudaFuncSetAttribute((const void*)hmma_gemm<128, false, false, true >, cudaFuncAttributeMaxDynamicSharedMemorySize, SM128);
    cudaFuncSetAttribute((const void*)hmma_gemm<64,  false, false, false>, cudaFuncAttributeMaxDynamicSharedMemorySize, SM64);
    cudaFuncSetAttribute((const void*)hmma_gemm<128, true,  false, true >, cudaFuncAttributeMaxDynamicSharedMemorySize, SM128);
    cudaFuncSetAttribute((const void*)hmma_gemm<128, true,  true,  false>, cudaFuncAttributeMaxDynamicSharedMemorySize, SM128);

    // --- weight prep: transpose + hi/lo split ---
    tsplit_w<<<dim3(32, 2, 16), 256>>>(Wq, wh + WQKV,               wl + WQKV,               64, 1024, 65536, 65536);
    tsplit_w<<<dim3(32, 2, 16), 256>>>(Wk, wh + WQKV + 1024 * 1024, wl + WQKV + 1024 * 1024, 64, 1024, 65536, 65536);
    tsplit_w<<<dim3(32, 2, 16), 256>>>(Wv, wh + WQKV + 2048 * 1024, wl + WQKV + 2048 * 1024, 64, 1024, 65536, 65536);
    tsplit_w<<<dim3(32, 32, 1), 256>>>(Wo, wh + WO,  wl + WO,  1024, 1024, 0, 0);
    tsplit_w<<<dim3(32, 128, 1), 256>>>(W1, wh + W1O, wl + W1O, 4096, 1024, 0, 0);
    tsplit_w<<<dim3(128, 32, 1), 256>>>(W2, wh + W2O, wl + W2O, 1024, 4096, 0, 0);
    biaspack<<<12, 256>>>(bq, bk, bv, bias);
    xsplit<<<4096, 256>>>(X, xh, xl, kM * kD / 4);

    // --- fused QKV: [4096,1024] x [3072,1024]^T ---
    hmma_gemm<128, true, false, false><<<dim3(24, 32, 1), 256, SM128>>>(
        xh, xl, wh + WQKV, wl + WQKV, bias, nullptr, qh, ql,
        1024, 1024, 1024, 3072, 0, 0, 0, 0, 0, 0, 1, 1.0f);

    vtrans<<<dim3(64, 2, 32), 256>>>(qh, ql, vth, vtl);

    // --- scores = (Q K^T)/8, batched over 32 (b,h) ---
    hmma_gemm<128, false, false, true><<<dim3(16, 16, 32), 256, SM128>>>(
        qh, ql, qh + 1024, ql + 1024, nullptr, sc, nullptr, nullptr,
        64, 3072, 3072, 2048,
        (long long)2048 * 3072, 64, (long long)2048 * 3072, 64,
        (long long)16 * 2048 * 2048, (long long)2048 * 2048, 16, 0.125f);

    softmax_hl<<<kB * kH * kS, 256>>>(sc, ph, pl);

    // --- attn = P V ---
    hmma_gemm<64, false, false, false><<<dim3(1, 16, 32), 128, SM64>>>(
        ph, pl, vth, vtl, nullptr, nullptr, ah, al,
        2048, 2048, 2048, 1024,
        (long long)16 * 2048 * 2048, (long long)2048 * 2048,
        (long long)16 * 64 * 2048, (long long)64 * 2048,
        (long long)2048 * 1024, 64, 16, 1.0f);

    // --- out projection ---
    hmma_gemm<128, true, false, true><<<dim3(8, 32, 1), 256, SM128>>>(
        ah, al, wh + WO, wl + WO, bo, pr, nullptr, nullptr,
        1024, 1024, 1024, 1024, 0, 0, 0, 0, 0, 0, 1, 1.0f);

    add_ln<true><<<kM, 256>>>(X, pr, l1g, l1b, y, yh, yl);

    // --- FFN1 (relu) ---
    hmma_gemm<128, true, true, false><<<dim3(32, 32, 1), 256, SM128>>>(
        yh, yl, wh + W1O, wl + W1O, b1, nullptr, f1h, f1l,
        1024, 1024, 1024, 4096, 0, 0, 0, 0, 0, 0, 1, 1.0f);

    // --- FFN2 ---
    hmma_gemm<128, true, false, true><<<dim3(8, 32, 1), 256, SM128>>>(
        f1h, f1l, wh + W2O, wl + W2O, b2, f2, nullptr, nullptr,
        4096, 4096, 4096, 1024, 0, 0, 0, 0, 0, 0, 1, 1.0f);

    add_ln<false><<<kM, 256>>>(y, f2, l2g, l2b, out, nullptr, nullptr);
}

// round 10
// speedup vs baseline: 3.0507x; 1.1654x over previous
#include <cuda_runtime.h>
#include <cuda_bf16.h>
#include <cstdint>

using bf16 = __nv_bfloat16;

constexpr int kB = 2, kS = 2048, kD = 1024, kH = 16, kHD = 64, kDFF = 4096;
constexpr int kM = kB * kS;
constexpr float kEps = 1e-5f;

constexpr long long WQKV = 0;            // [3072][1024]
constexpr long long WO   = 3145728;      // [1024][1024]
constexpr long long W1O  = 4194304;      // [4096][1024]
constexpr long long W2O  = 8388608;      // [1024][4096]
constexpr long long WTOT = 12582912;

__device__ bf16  g_wh[WTOT], g_wl[WTOT];
__device__ float g_bias[3072];
__device__ bf16  g_xh[4194304], g_xl[4194304];
__device__ bf16  g_qh[12582912], g_ql[12582912];     // fused QKV out [4096][3072]
__device__ bf16  g_ah[4194304], g_al[4194304];       // attn out [4096][1024]
__device__ float g_pr[4194304];
__device__ float g_y[4194304];
__device__ bf16  g_yh[4194304], g_yl[4194304];
__device__ bf16  g_f1h[16777216], g_f1l[16777216];   // [4096][4096]
__device__ float g_f2[4194304];

// ---------------- helpers ----------------
__device__ __forceinline__ uint32_t smem_u32(const void* p) {
    uint32_t a;
    asm("{ .reg .u64 t; cvta.to.shared.u64 t, %1; cvt.u32.u64 %0, t; }" : "=r"(a) : "l"(p));
    return a;
}
__device__ __forceinline__ void cp16(uint32_t s, const void* g) {
    asm volatile("cp.async.cg.shared.global [%0], [%1], 16;" :: "r"(s), "l"(g));
}
#define CP_COMMIT() asm volatile("cp.async.commit_group;" ::: "memory")
#define CP_WAIT(n)  asm volatile("cp.async.wait_group %0;" :: "n"(n) : "memory")
__device__ __forceinline__ uint32_t swz(uint32_t o) { return o ^ ((o >> 3) & 0x70); }

__device__ __forceinline__ void ldm4(uint32_t* r, uint32_t a) {
    asm volatile("ldmatrix.sync.aligned.m8n8.x4.shared.b16 {%0,%1,%2,%3}, [%4];"
                 : "=r"(r[0]), "=r"(r[1]), "=r"(r[2]), "=r"(r[3]) : "r"(a));
}
__device__ __forceinline__ void ldm4t(uint32_t* r, uint32_t a) {
    asm volatile("ldmatrix.sync.aligned.m8n8.x4.trans.shared.b16 {%0,%1,%2,%3}, [%4];"
                 : "=r"(r[0]), "=r"(r[1]), "=r"(r[2]), "=r"(r[3]) : "r"(a));
}
__device__ __forceinline__ void ldm2(uint32_t* r, uint32_t a) {
    asm volatile("ldmatrix.sync.aligned.m8n8.x2.shared.b16 {%0,%1}, [%2];"
                 : "=r"(r[0]), "=r"(r[1]) : "r"(a));
}
__device__ __forceinline__ void mma16816(float* c, const uint32_t* a, const uint32_t* b) {
    asm volatile("mma.sync.aligned.m16n8k16.row.col.f32.bf16.bf16.f32 "
                 "{%0,%1,%2,%3}, {%4,%5,%6,%7}, {%8,%9}, {%0,%1,%2,%3};"
                 : "+f"(c[0]), "+f"(c[1]), "+f"(c[2]), "+f"(c[3])
                 : "r"(a[0]), "r"(a[1]), "r"(a[2]), "r"(a[3]), "r"(b[0]), "r"(b[1]));
}
__device__ __forceinline__ uint32_t packhl(float a, float b, bool hi) {
    __nv_bfloat162 t;
    bf16 ha = __float2bfloat16(a), hb = __float2bfloat16(b);
    if (hi) { t.x = ha; t.y = hb; }
    else { t.x = __float2bfloat16(a - __bfloat162float(ha)); t.y = __float2bfloat16(b - __bfloat162float(hb)); }
    return *reinterpret_cast<uint32_t*>(&t);
}
// fast exp on the FMA pipe (no MUFU): 2^t with deg-5 poly, rel err ~2e-6
__device__ __forceinline__ float fexp(float x) {
    x = fmaxf(x, -80.0f);
    float t = x * 1.4426950408889634f;
    int ni = __float2int_rn(t);
    float f = t - (float)ni;
    float p = 1.33355815e-3f;
    p = fmaf(p, f, 9.61812910e-3f);
    p = fmaf(p, f, 5.55041087e-2f);
    p = fmaf(p, f, 2.40226507e-1f);
    p = fmaf(p, f, 6.93147181e-1f);
    p = fmaf(p, f, 1.0f);
    return p * __int_as_float((ni + 127) << 23);
}

// ---------------------------------------------------------------------------
// HMMA split-bf16 GEMM (unchanged from R6 winner)
// ---------------------------------------------------------------------------
template <int BN, bool BIAS, bool RELU, bool WF32>
__global__ __launch_bounds__(BN == 128 ? 256 : 128)
void hmma_gemm(const bf16* __restrict__ Ah, const bf16* __restrict__ Al,
               const bf16* __restrict__ Bh, const bf16* __restrict__ Bl,
               const float* __restrict__ bias,
               float* __restrict__ Cf, bf16* __restrict__ Ch, bf16* __restrict__ Cl,
               int K, int lda, int ldb, int ldc,
               long long sA1, long long sA2, long long sB1, long long sB2,
               long long sC1, long long sC2, int bdiv, float alpha)
{
    constexpr int THREADS = (BN == 128) ? 256 : 128;
    constexpr int WN = (BN == 128) ? 4 : 2;
    constexpr int AST = 128 * 128;
    constexpr int BST = BN * 128;
    constexpr int STAGE = 2 * AST + 2 * BST;

    extern __shared__ char smem[];
    const uint32_t st0 = (smem_u32(smem) + 127u) & ~127u;

    const int tid = threadIdx.x, wid = tid >> 5, lid = tid & 31;
    const int z = blockIdx.z, zb = z / bdiv, zh = z - zb * bdiv;
    Ah += zb * sA1 + zh * sA2;  Al += zb * sA1 + zh * sA2;
    Bh += zb * sB1 + zh * sB2;  Bl += zb * sB1 + zh * sB2;
    const long long cOff = zb * sC1 + zh * sC2;
    const int m0 = blockIdx.y * 128, n0 = blockIdx.x * BN;
    const int wm0 = (wid / WN) * 64, wn0 = (wid % WN) * 32;

    const int nk = K >> 6;

    auto load = [&](int s) {
        uint32_t aH = st0 + (s & 1) * STAGE, aL = aH + AST, bH = aL + AST, bL = bH + BST;
        const int k0 = s << 6;
#pragma unroll
        for (int c = tid; c < 1024; c += THREADS) {
            int r = c >> 3, cj = c & 7;
            uint32_t so = swz((uint32_t)((r << 7) + (cj << 4)));
            long long go = (long long)(m0 + r) * lda + k0 + (cj << 3);
            cp16(aH + so, Ah + go);
            cp16(aL + so, Al + go);
        }
#pragma unroll
        for (int c = tid; c < BN * 8; c += THREADS) {
            int r = c >> 3, cj = c & 7;
            uint32_t so = swz((uint32_t)((r << 7) + (cj << 4)));
            long long go = (long long)(n0 + r) * ldb + k0 + (cj << 3);
            cp16(bH + so, Bh + go);
            cp16(bL + so, Bl + go);
        }
    };

    float acc[4][4][4];
#pragma unroll
    for (int i = 0; i < 4; ++i)
#pragma unroll
        for (int j = 0; j < 4; ++j)
#pragma unroll
            for (int q = 0; q < 4; ++q) acc[i][j][q] = 0.0f;

    load(0); CP_COMMIT();

    for (int it = 0; it < nk; ++it) {
        if (it + 1 < nk) { load(it + 1); CP_COMMIT(); CP_WAIT(1); }
        else             { CP_WAIT(0); }
        __syncthreads();

        uint32_t aH = st0 + (it & 1) * STAGE, aL = aH + AST, bH = aL + AST, bL = bH + BST;
#pragma unroll
        for (int k16 = 0; k16 < 4; ++k16) {
            uint32_t ah[4][4], al[4][4], bh[4][2], bl[4][2];
#pragma unroll
            for (int mi = 0; mi < 4; ++mi) {
                uint32_t byte = (uint32_t)((wm0 + mi * 16 + (lid & 15)) << 7)
                              + (uint32_t)((k16 * 2 + (lid >> 4)) << 4);
                uint32_t so = swz(byte);
                ldm4(ah[mi], aH + so);
                ldm4(al[mi], aL + so);
            }
#pragma unroll
            for (int ni = 0; ni < 4; ++ni) {
                uint32_t byte = (uint32_t)((wn0 + ni * 8 + (lid & 7)) << 7)
                              + (uint32_t)((k16 * 2 + ((lid >> 3) & 1)) << 4);
                uint32_t so = swz(byte);
                ldm2(bh[ni], bH + so);
                ldm2(bl[ni], bL + so);
            }
#pragma unroll
            for (int mi = 0; mi < 4; ++mi)
#pragma unroll
                for (int ni = 0; ni < 4; ++ni) mma16816(acc[mi][ni], ah[mi], bh[ni]);
#pragma unroll
            for (int mi = 0; mi < 4; ++mi)
#pragma unroll
                for (int ni = 0; ni < 4; ++ni) mma16816(acc[mi][ni], ah[mi], bl[ni]);
#pragma unroll
            for (int mi = 0; mi < 4; ++mi)
#pragma unroll
                for (int ni = 0; ni < 4; ++ni) mma16816(acc[mi][ni], al[mi], bh[ni]);
        }
        __syncthreads();
    }

#pragma unroll
    for (int mi = 0; mi < 4; ++mi) {
        const int gm = m0 + wm0 + mi * 16 + (lid >> 2);
#pragma unroll
        for (int ni = 0; ni < 4; ++ni) {
            const int gn = n0 + wn0 + ni * 8 + ((lid & 3) << 1);
            float v0 = acc[mi][ni][0] * alpha, v1 = acc[mi][ni][1] * alpha;
            float v2 = acc[mi][ni][2] * alpha, v3 = acc[mi][ni][3] * alpha;
            if (BIAS) {
                float b0 = bias[gn], b1 = bias[gn + 1];
                v0 += b0; v1 += b1; v2 += b0; v3 += b1;
            }
            if (RELU) {
                v0 = fmaxf(v0, 0.0f); v1 = fmaxf(v1, 0.0f);
                v2 = fmaxf(v2, 0.0f); v3 = fmaxf(v3, 0.0f);
            }
            if (WF32) {
                float2* p0 = reinterpret_cast<float2*>(Cf + cOff + (long long)gm * ldc + gn);
                float2* p1 = reinterpret_cast<float2*>(Cf + cOff + (long long)(gm + 8) * ldc + gn);
                *p0 = make_float2(v0, v1);
                *p1 = make_float2(v2, v3);
            } else {
                *reinterpret_cast<uint32_t*>(Ch + cOff + (long long)gm * ldc + gn)       = packhl(v0, v1, true);
                *reinterpret_cast<uint32_t*>(Cl + cOff + (long long)gm * ldc + gn)       = packhl(v0, v1, false);
                *reinterpret_cast<uint32_t*>(Ch + cOff + (long long)(gm + 8) * ldc + gn) = packhl(v2, v3, true);
                *reinterpret_cast<uint32_t*>(Cl + cOff + (long long)(gm + 8) * ldc + gn) = packhl(v2, v3, false);
            }
        }
    }
}

// ---------------------------------------------------------------------------
// Flash attention: per CTA one (b,h) x 128 q-rows. 8 warps x 16 rows.
// K/V streamed in 128-key tiles (double buffered) from the fused QKV buffer.
// S and P in registers; 3-term split-bf16 for both QK^T and PV.
// ---------------------------------------------------------------------------
__global__ __launch_bounds__(256)
void flash_attn(const bf16* __restrict__ qkvh, const bf16* __restrict__ qkvl,
                bf16* __restrict__ oh, bf16* __restrict__ ol)
{
    constexpr int LDA = 3072;
    extern __shared__ char smem[];
    const uint32_t sQh = (smem_u32(smem) + 127u) & ~127u;
    const uint32_t sQl = sQh + 16384;
    const uint32_t sKV = sQl + 16384;          // + (stage)*65536 ; K:0 Kl:16K V:32K Vl:48K

    const int tid = threadIdx.x, wid = tid >> 5, lid = tid & 31;
    const int q0 = blockIdx.x * 128;
    const int z = blockIdx.y, b = z >> 4, h = z & 15;
    const long long base = (long long)b * 2048 * LDA + h * 64;
    const bf16* Qh = qkvh + base;        const bf16* Ql = qkvl + base;
    const bf16* Kh = qkvh + base + 1024; const bf16* Kl = qkvl + base + 1024;
    const bf16* Vh = qkvh + base + 2048; const bf16* Vl = qkvl + base + 2048;

    auto loadQ = [&]() {
#pragma unroll
        for (int i = 0; i < 4; ++i) {
            int c = tid + i * 256; int r = c >> 3, cj = c & 7;
            uint32_t so = swz((uint32_t)((r << 7) + (cj << 4)));
            long long go = (long long)(q0 + r) * LDA + (cj << 3);
            cp16(sQh + so, Qh + go);
            cp16(sQl + so, Ql + go);
        }
    };
    auto loadKV = [&](int t) {
        uint32_t st = sKV + (uint32_t)(t & 1) * 65536u;
        const int kr = t * 128;
#pragma unroll
        for (int i = 0; i < 4; ++i) {
            int c = tid + i * 256; int r = c >> 3, cj = c & 7;
            uint32_t so = swz((uint32_t)((r << 7) + (cj << 4)));
            long long go = (long long)(kr + r) * LDA + (cj << 3);
            cp16(st + so,          Kh + go);
            cp16(st + 16384 + so,  Kl + go);
            cp16(st + 32768 + so,  Vh + go);
            cp16(st + 49152 + so,  Vl + go);
        }
    };

    const int wq = wid * 16;
    float oacc[8][4];
#pragma unroll
    for (int n = 0; n < 8; ++n)
#pragma unroll
        for (int q = 0; q < 4; ++q) oacc[n][q] = 0.0f;
    float m0r = -1e30f, m1r = -1e30f, l0 = 0.0f, l1 = 0.0f;
    uint32_t qah[4][4], qal[4][4];

    loadQ(); loadKV(0); CP_COMMIT();

    for (int t = 0; t < 16; ++t) {
        if (t + 1 < 16) { loadKV(t + 1); CP_COMMIT(); CP_WAIT(1); }
        else            { CP_WAIT(0); }
        __syncthreads();

        if (t == 0) {
#pragma unroll
            for (int k16 = 0; k16 < 4; ++k16) {
                uint32_t byte = (uint32_t)((wq + (lid & 15)) << 7)
                              + (uint32_t)((k16 * 2 + (lid >> 4)) << 4);
                uint32_t so = swz(byte);
                ldm4(qah[k16], sQh + so);
                ldm4(qal[k16], sQl + so);
            }
        }

        const uint32_t stK = sKV + (uint32_t)(t & 1) * 65536u;
        const uint32_t stV = stK + 32768;

        // ---- S = Q K^T (16 n8-tiles over 128 keys) ----
        float sacc[16][4];
#pragma unroll
        for (int i = 0; i < 16; ++i)
#pragma unroll
            for (int q = 0; q < 4; ++q) sacc[i][q] = 0.0f;

        const int grp = lid >> 3, rowIn = lid & 7;
#pragma unroll
        for (int k16 = 0; k16 < 4; ++k16) {
#pragma unroll
            for (int np = 0; np < 8; ++np) {          // 2 n8-tiles per pair
                uint32_t bfh[4], bfl[4];
                int n = np * 16 + ((grp >> 1) << 3) + rowIn;
                int chunk = k16 * 2 + (grp & 1);
                uint32_t so = swz((uint32_t)((n << 7) + (chunk << 4)));
                ldm4(bfh, stK + so);
                ldm4(bfl, stK + 16384 + so);
                mma16816(sacc[np * 2],     qah[k16], bfh);
                mma16816(sacc[np * 2],     qah[k16], bfl);
                mma16816(sacc[np * 2],     qal[k16], bfh);
                mma16816(sacc[np * 2 + 1], qah[k16], bfh + 2);
                mma16816(sacc[np * 2 + 1], qah[k16], bfl + 2);
                mma16816(sacc[np * 2 + 1], qal[k16], bfh + 2);
            }
        }

        // ---- online softmax ----
        float mn0 = m0r, mn1 = m1r;
#pragma unroll
        for (int i = 0; i < 16; ++i) {
            sacc[i][0] *= 0.125f; sacc[i][1] *= 0.125f;
            sacc[i][2] *= 0.125f; sacc[i][3] *= 0.125f;
            mn0 = fmaxf(mn0, fmaxf(sacc[i][0], sacc[i][1]));
            mn1 = fmaxf(mn1, fmaxf(sacc[i][2], sacc[i][3]));
        }
        mn0 = fmaxf(mn0, __shfl_xor_sync(0xFFFFFFFFu, mn0, 1));
        mn0 = fmaxf(mn0, __shfl_xor_sync(0xFFFFFFFFu, mn0, 2));
        mn1 = fmaxf(mn1, __shfl_xor_sync(0xFFFFFFFFu, mn1, 1));
        mn1 = fmaxf(mn1, __shfl_xor_sync(0xFFFFFFFFu, mn1, 2));
        float a0 = fexp(m0r - mn0), a1 = fexp(m1r - mn1);
        m0r = mn0; m1r = mn1;
#pragma unroll
        for (int n = 0; n < 8; ++n) {
            oacc[n][0] *= a0; oacc[n][1] *= a0;
            oacc[n][2] *= a1; oacc[n][3] *= a1;
        }
        float rs0 = 0.0f, rs1 = 0.0f;

        // ---- P chunks -> O += P V ----
#pragma unroll
        for (int j = 0; j < 8; ++j) {                 // k16 of keys
            float p0 = fexp(sacc[2 * j][0] - m0r), p1 = fexp(sacc[2 * j][1] - m0r);
            float p2 = fexp(sacc[2 * j][2] - m1r), p3 = fexp(sacc[2 * j][3] - m1r);
            float p4 = fexp(sacc[2 * j + 1][0] - m0r), p5 = fexp(sacc[2 * j + 1][1] - m0r);
            float p6 = fexp(sacc[2 * j + 1][2] - m1r), p7 = fexp(sacc[2 * j + 1][3] - m1r);
            rs0 += p0 + p1 + p4 + p5;
            rs1 += p2 + p3 + p6 + p7;
            uint32_t pah[4], pal[4];
            pah[0] = packhl(p0, p1, true);  pal[0] = packhl(p0, p1, false);
            pah[1] = packhl(p2, p3, true);  pal[1] = packhl(p2, p3, false);
            pah[2] = packhl(p4, p5, true);  pal[2] = packhl(p4, p5, false);
            pah[3] = packhl(p6, p7, true);  pal[3] = packhl(p6, p7, false);
#pragma unroll
            for (int hp = 0; hp < 4; ++hp) {          // 2 hd n8-tiles per pair
                uint32_t bfh[4], bfl[4];
                int key = j * 16 + ((grp & 1) << 3) + rowIn;
                int chunk = hp * 2 + (grp >> 1);
                uint32_t so = swz((uint32_t)((key << 7) + (chunk << 4)));
                ldm4t(bfh, stV + so);
                ldm4t(bfl, stV + 16384 + so);
                mma16816(oacc[hp * 2],     pah, bfh);
                mma16816(oacc[hp * 2],     pah, bfl);
                mma16816(oacc[hp * 2],     pal, bfh);
                mma16816(oacc[hp * 2 + 1], pah, bfh + 2);
                mma16816(oacc[hp * 2 + 1], pah, bfl + 2);
                mma16816(oacc[hp * 2 + 1], pal, bfh + 2);
            }
        }
        rs0 += __shfl_xor_sync(0xFFFFFFFFu, rs0, 1);
        rs0 += __shfl_xor_sync(0xFFFFFFFFu, rs0, 2);
        rs1 += __shfl_xor_sync(0xFFFFFFFFu, rs1, 1);
        rs1 += __shfl_xor_sync(0xFFFFFFFFu, rs1, 2);
        l0 = l0 * a0 + rs0;
        l1 = l1 * a1 + rs1;
        __syncthreads();
    }

    // ---- epilogue: O /= l, write hi/lo bf16 ----
    const float inv0 = 1.0f / l0, inv1 = 1.0f / l1;
    const int gm0 = b * 2048 + q0 + wq + (lid >> 2);
    const int gnb = h * 64 + ((lid & 3) << 1);
#pragma unroll
    for (int n = 0; n < 8; ++n) {
        float v0 = oacc[n][0] * inv0, v1 = oacc[n][1] * inv0;
        float v2 = oacc[n][2] * inv1, v3 = oacc[n][3] * inv1;
        int gn = gnb + n * 8;
        *reinterpret_cast<uint32_t*>(oh + (long long)gm0 * 1024 + gn)       = packhl(v0, v1, true);
        *reinterpret_cast<uint32_t*>(ol + (long long)gm0 * 1024 + gn)       = packhl(v0, v1, false);
        *reinterpret_cast<uint32_t*>(oh + (long long)(gm0 + 8) * 1024 + gn) = packhl(v2, v3, true);
        *reinterpret_cast<uint32_t*>(ol + (long long)(gm0 + 8) * 1024 + gn) = packhl(v2, v3, false);
    }
}

// ---------------- prep kernels ----------------
__global__ __launch_bounds__(256)
void tsplit_w(const float* __restrict__ in, bf16* __restrict__ oh, bf16* __restrict__ ol,
              int ldi, int ldo, long long ibs, long long obs)
{
    __shared__ float t[32][33];
    const int z = blockIdx.z;
    const float* ip = in + z * ibs;
    bf16 *ohp = oh + z * obs, *olp = ol + z * obs;
    const int r0 = blockIdx.x * 32, c0 = blockIdx.y * 32;
    const int tx = threadIdx.x & 31, ty = threadIdx.x >> 5;
#pragma unroll
    for (int j = 0; j < 32; j += 8)
        t[ty + j][tx] = ip[(long long)(r0 + ty + j) * ldi + c0 + tx];
    __syncthreads();
#pragma unroll
    for (int j = 0; j < 32; j += 8) {
        float v = t[tx][ty + j];
        bf16 hh = __float2bfloat16(v);
        long long o = (long long)(c0 + ty + j) * ldo + r0 + tx;
        ohp[o] = hh;
        olp[o] = __float2bfloat16(v - __bfloat162float(hh));
    }
}

__global__ void biaspack(const float* q, const float* k, const float* v, float* o)
{
    int i = blockIdx.x * 256 + threadIdx.x;
    if (i < 1024) o[i] = q[i];
    else if (i < 2048) o[i] = k[i - 1024];
    else if (i < 3072) o[i] = v[i - 2048];
}

__global__ __launch_bounds__(256)
void xsplit(const float* __restrict__ in, bf16* __restrict__ oh, bf16* __restrict__ ol, int n4)
{
    int i = blockIdx.x * 256 + threadIdx.x;
    if (i >= n4) return;
    float4 v = reinterpret_cast<const float4*>(in)[i];
    uint2 uh = { packhl(v.x, v.y, true),  packhl(v.z, v.w, true)  };
    uint2 ul = { packhl(v.x, v.y, false), packhl(v.z, v.w, false) };
    reinterpret_cast<uint2*>(oh)[i] = uh;
    reinterpret_cast<uint2*>(ol)[i] = ul;
}

template <bool SPLIT>
__global__ __launch_bounds__(256)
void add_ln(const float* __restrict__ x, const float* __restrict__ d,
            const float* __restrict__ g, const float* __restrict__ b,
            float* __restrict__ out, bf16* __restrict__ oh, bf16* __restrict__ ol)
{
    const long long row = blockIdx.x;
    const int tid = threadIdx.x;
    const float4* x4 = reinterpret_cast<const float4*>(x) + row * 256;
    const float4* d4 = reinterpret_cast<const float4*>(d) + row * 256;
    float4 xv = x4[tid], dv = d4[tid], v;
    v.x = xv.x + dv.x; v.y = xv.y + dv.y; v.z = xv.z + dv.z; v.w = xv.w + dv.w;

    __shared__ float rs[256], rq[256];
    rs[tid] = v.x + v.y + v.z + v.w;
    rq[tid] = v.x * v.x + v.y * v.y + v.z * v.z + v.w * v.w;
    __syncthreads();
    for (int o = 128; o > 0; o >>= 1) {
        if (tid < o) { rs[tid] += rs[tid + o]; rq[tid] += rq[tid + o]; }
        __syncthreads();
    }
    const float mean = rs[0] * (1.0f / kD);
    const float rstd = rsqrtf(rq[0] * (1.0f / kD) - mean * mean + kEps);

    float4 gv = reinterpret_cast<const float4*>(g)[tid];
    float4 bv = reinterpret_cast<const float4*>(b)[tid];
    float4 ov;
    ov.x = (v.x - mean) * rstd * gv.x + bv.x;
    ov.y = (v.y - mean) * rstd * gv.y + bv.y;
    ov.z = (v.z - mean) * rstd * gv.z + bv.z;
    ov.w = (v.w - mean) * rstd * gv.w + bv.w;
    reinterpret_cast<float4*>(out)[row * 256 + tid] = ov;
    if (SPLIT) {
        uint2 uh = { packhl(ov.x, ov.y, true),  packhl(ov.z, ov.w, true)  };
        uint2 ul = { packhl(ov.x, ov.y, false), packhl(ov.z, ov.w, false) };
        reinterpret_cast<uint2*>(oh)[row * 256 + tid] = uh;
        reinterpret_cast<uint2*>(ol)[row * 256 + tid] = ul;
    }
}

// ---------------------------------------------------------------------------
extern "C" void kernel_launch(void* const* d_in, const int* in_sizes, int n_in,
                              void* d_out, int out_size)
{
    (void)in_sizes; (void)n_in; (void)out_size;
    const float* X  = (const float*)d_in[0];
    const float* Wq = (const float*)d_in[1];  const float* bq = (const float*)d_in[2];
    const float* Wk = (const float*)d_in[3];  const float* bk = (const float*)d_in[4];
    const float* Wv = (const float*)d_in[5];  const float* bv = (const float*)d_in[6];
    const float* Wo = (const float*)d_in[7];  const float* bo = (const float*)d_in[8];
    const float* l1g = (const float*)d_in[9]; const float* l1b = (const float*)d_in[10];
    const float* W1 = (const float*)d_in[11]; const float* b1 = (const float*)d_in[12];
    const float* W2 = (const float*)d_in[13]; const float* b2 = (const float*)d_in[14];
    const float* l2g = (const float*)d_in[15]; const float* l2b = (const float*)d_in[16];
    float* out = (float*)d_out;

    bf16 *wh, *wl, *xh, *xl, *qh, *ql, *ah, *al, *yh, *yl, *f1h, *f1l;
    float *bias, *pr, *y, *f2;
    cudaGetSymbolAddress((void**)&wh, g_wh);   cudaGetSymbolAddress((void**)&wl, g_wl);
    cudaGetSymbolAddress((void**)&bias, g_bias);
    cudaGetSymbolAddress((void**)&xh, g_xh);   cudaGetSymbolAddress((void**)&xl, g_xl);
    cudaGetSymbolAddress((void**)&qh, g_qh);   cudaGetSymbolAddress((void**)&ql, g_ql);
    cudaGetSymbolAddress((void**)&ah, g_ah);   cudaGetSymbolAddress((void**)&al, g_al);
    cudaGetSymbolAddress((void**)&pr, g_pr);   cudaGetSymbolAddress((void**)&y, g_y);
    cudaGetSymbolAddress((void**)&yh, g_yh);   cudaGetSymbolAddress((void**)&yl, g_yl);
    cudaGetSymbolAddress((void**)&f1h, g_f1h); cudaGetSymbolAddress((void**)&f1l, g_f1l);
    cudaGetSymbolAddress((void**)&f2, g_f2);

    constexpr int SM128 = 2 * (2 * 16384 + 2 * 16384) + 128;   // 131200
    constexpr int FSM   = 2 * 16384 + 2 * 65536 + 128;         // 163968
    cudaFuncSetAttribute((const void*)hmma_gemm<128, true,  false, false>, cudaFuncAttributeMaxDynamicSharedMemorySize, SM128);
    cudaFuncSetAttribute((const void*)hmma_gemm<128, true,  false, true >, cudaFuncAttributeMaxDynamicSharedMemorySize, SM128);
    cudaFuncSetAttribute((const void*)hmma_gemm<128, true,  true,  false>, cudaFuncAttributeMaxDynamicSharedMemorySize, SM128);
    cudaFuncSetAttribute((const void*)flash_attn, cudaFuncAttributeMaxDynamicSharedMemorySize, FSM);

    // --- weight prep: transpose + hi/lo split ---
    tsplit_w<<<dim3(32, 2, 16), 256>>>(Wq, wh + WQKV,               wl + WQKV,               64, 1024, 65536, 65536);
    tsplit_w<<<dim3(32, 2, 16), 256>>>(Wk, wh + WQKV + 1024 * 1024, wl + WQKV + 1024 * 1024, 64, 1024, 65536, 65536);
    tsplit_w<<<dim3(32, 2, 16), 256>>>(Wv, wh + WQKV + 2048 * 1024, wl + WQKV + 2048 * 1024, 64, 1024, 65536, 65536);
    tsplit_w<<<dim3(32, 32, 1), 256>>>(Wo, wh + WO,  wl + WO,  1024, 1024, 0, 0);
    tsplit_w<<<dim3(32, 128, 1), 256>>>(W1, wh + W1O, wl + W1O, 4096, 1024, 0, 0);
    tsplit_w<<<dim3(128, 32, 1), 256>>>(W2, wh + W2O, wl + W2O, 1024, 4096, 0, 0);
    biaspack<<<12, 256>>>(bq, bk, bv, bias);
    xsplit<<<4096, 256>>>(X, xh, xl, kM * kD / 4);

    // --- fused QKV: [4096,1024] x [3072,1024]^T ---
    hmma_gemm<128, true, false, false><<<dim3(24, 32, 1), 256, SM128>>>(
        xh, xl, wh + WQKV, wl + WQKV, bias, nullptr, qh, ql,
        1024, 1024, 1024, 3072, 0, 0, 0, 0, 0, 0, 1, 1.0f);

    // --- flash attention: QK^T -> softmax -> PV fused ---
    flash_attn<<<dim3(16, 32), 256, FSM>>>(qh, ql, ah, al);

    // --- out projection ---
    hmma_gemm<128, true, false, true><<<dim3(8, 32, 1), 256, SM128>>>(
        ah, al, wh + WO, wl + WO, bo, pr, nullptr, nullptr,
        1024, 1024, 1024, 1024, 0, 0, 0, 0, 0, 0, 1, 1.0f);

    add_ln<true><<<kM, 256>>>(X, pr, l1g, l1b, y, yh, yl);

    // --- FFN1 (relu) ---
    hmma_gemm<128, true, true, false><<<dim3(32, 32, 1), 256, SM128>>>(
        yh, yl, wh + W1O, wl + W1O, b1, nullptr, f1h, f1l,
        1024, 1024, 1024, 4096, 0, 0, 0, 0, 0, 0, 1, 1.0f);

    // --- FFN2 ---
    hmma_gemm<128, true, false, true><<<dim3(8, 32, 1), 256, SM128>>>(
        f1h, f1l, wh + W2O, wl + W2O, b2, f2, nullptr, nullptr,
        4096, 4096, 4096, 1024, 0, 0, 0, 0, 0, 0, 1, 1.0f);

    add_ln<false><<<kM, 256>>>(y, f2, l2g, l2b, out, nullptr, nullptr);
}

// round 11
// speedup vs baseline: 3.1365x; 1.0281x over previous
#include <cuda_runtime.h>
#include <cuda_bf16.h>
#include <cstdint>

using bf16 = __nv_bfloat16;

constexpr int kB = 2, kS = 2048, kD = 1024, kH = 16, kHD = 64, kDFF = 4096;
constexpr int kM = kB * kS;
constexpr float kEps = 1e-5f;

constexpr long long WQKV = 0;            // [3072][1024]
constexpr long long WO   = 3145728;      // [1024][1024]
constexpr long long W1O  = 4194304;      // [4096][1024]
constexpr long long W2O  = 8388608;      // [1024][4096]
constexpr long long WTOT = 12582912;

__device__ bf16  g_wh[WTOT], g_wl[WTOT];
__device__ float g_bias[3072];
__device__ bf16  g_xh[4194304], g_xl[4194304];
__device__ bf16  g_qh[12582912], g_ql[12582912];     // fused QKV out [4096][3072]
__device__ bf16  g_ah[4194304], g_al[4194304];       // attn out [4096][1024]
__device__ float g_pr[4194304];
__device__ float g_y[4194304];
__device__ bf16  g_yh[4194304], g_yl[4194304];
__device__ bf16  g_f1h[16777216], g_f1l[16777216];   // [4096][4096]
__device__ float g_f2[4194304];

// ---------------- helpers ----------------
__device__ __forceinline__ uint32_t smem_u32(const void* p) {
    uint32_t a;
    asm("{ .reg .u64 t; cvta.to.shared.u64 t, %1; cvt.u32.u64 %0, t; }" : "=r"(a) : "l"(p));
    return a;
}
__device__ __forceinline__ void cp16(uint32_t s, const void* g) {
    asm volatile("cp.async.cg.shared.global [%0], [%1], 16;" :: "r"(s), "l"(g));
}
#define CP_COMMIT() asm volatile("cp.async.commit_group;" ::: "memory")
#define CP_WAIT(n)  asm volatile("cp.async.wait_group %0;" :: "n"(n) : "memory")
__device__ __forceinline__ uint32_t swz(uint32_t o) { return o ^ ((o >> 3) & 0x70); }

__device__ __forceinline__ void ldm4(uint32_t* r, uint32_t a) {
    asm volatile("ldmatrix.sync.aligned.m8n8.x4.shared.b16 {%0,%1,%2,%3}, [%4];"
                 : "=r"(r[0]), "=r"(r[1]), "=r"(r[2]), "=r"(r[3]) : "r"(a));
}
__device__ __forceinline__ void ldm4t(uint32_t* r, uint32_t a) {
    asm volatile("ldmatrix.sync.aligned.m8n8.x4.trans.shared.b16 {%0,%1,%2,%3}, [%4];"
                 : "=r"(r[0]), "=r"(r[1]), "=r"(r[2]), "=r"(r[3]) : "r"(a));
}
__device__ __forceinline__ void mma16816(float* c, const uint32_t* a, const uint32_t* b) {
    asm volatile("mma.sync.aligned.m16n8k16.row.col.f32.bf16.bf16.f32 "
                 "{%0,%1,%2,%3}, {%4,%5,%6,%7}, {%8,%9}, {%0,%1,%2,%3};"
                 : "+f"(c[0]), "+f"(c[1]), "+f"(c[2]), "+f"(c[3])
                 : "r"(a[0]), "r"(a[1]), "r"(a[2]), "r"(a[3]), "r"(b[0]), "r"(b[1]));
}
__device__ __forceinline__ uint32_t packhl(float a, float b, bool hi) {
    __nv_bfloat162 t;
    bf16 ha = __float2bfloat16(a), hb = __float2bfloat16(b);
    if (hi) { t.x = ha; t.y = hb; }
    else { t.x = __float2bfloat16(a - __bfloat162float(ha)); t.y = __float2bfloat16(b - __bfloat162float(hb)); }
    return *reinterpret_cast<uint32_t*>(&t);
}
// fast exp on the FMA pipe (no MUFU): 2^t with deg-5 poly, rel err ~2e-6
__device__ __forceinline__ float fexp(float x) {
    x = fmaxf(x, -80.0f);
    float t = x * 1.4426950408889634f;
    int ni = __float2int_rn(t);
    float f = t - (float)ni;
    float p = 1.33355815e-3f;
    p = fmaf(p, f, 9.61812910e-3f);
    p = fmaf(p, f, 5.55041087e-2f);
    p = fmaf(p, f, 2.40226507e-1f);
    p = fmaf(p, f, 6.93147181e-1f);
    p = fmaf(p, f, 1.0f);
    return p * __int_as_float((ni + 127) << 23);
}

// ---------------------------------------------------------------------------
// HMMA split-bf16 GEMM. R11: 3-stage cp.async pipeline, ONE sync per K-iter,
// B fragments via paired ldm4 (lane mapping proven by the passing flash kernel).
// BM=128, BN=128, BK=64. 256 threads (8 warps, 2x4 warp grid, warp tile 64x32).
// ---------------------------------------------------------------------------
template <int BN, bool BIAS, bool RELU, bool WF32>
__global__ __launch_bounds__(256)
void hmma_gemm(const bf16* __restrict__ Ah, const bf16* __restrict__ Al,
               const bf16* __restrict__ Bh, const bf16* __restrict__ Bl,
               const float* __restrict__ bias,
               float* __restrict__ Cf, bf16* __restrict__ Ch, bf16* __restrict__ Cl,
               int K, int lda, int ldb, int ldc,
               long long sA1, long long sA2, long long sB1, long long sB2,
               long long sC1, long long sC2, int bdiv, float alpha)
{
    constexpr int THREADS = 256;
    constexpr int WN = 4;
    constexpr int AST = 128 * 128;
    constexpr int BST = BN * 128;
    constexpr int STAGE = 2 * AST + 2 * BST;   // 64 KB for BN=128

    extern __shared__ char smem[];
    const uint32_t st0 = (smem_u32(smem) + 127u) & ~127u;

    const int tid = threadIdx.x, wid = tid >> 5, lid = tid & 31;
    const int z = blockIdx.z, zb = z / bdiv, zh = z - zb * bdiv;
    Ah += zb * sA1 + zh * sA2;  Al += zb * sA1 + zh * sA2;
    Bh += zb * sB1 + zh * sB2;  Bl += zb * sB1 + zh * sB2;
    const long long cOff = zb * sC1 + zh * sC2;
    const int m0 = blockIdx.y * 128, n0 = blockIdx.x * BN;
    const int wm0 = (wid / WN) * 64, wn0 = (wid % WN) * 32;

    const int nk = K >> 6;

    auto load = [&](int s) {
        uint32_t aH = st0 + (uint32_t)(s % 3) * STAGE, aL = aH + AST, bH = aL + AST, bL = bH + BST;
        const int k0 = s << 6;
#pragma unroll
        for (int c = tid; c < 1024; c += THREADS) {
            int r = c >> 3, cj = c & 7;
            uint32_t so = swz((uint32_t)((r << 7) + (cj << 4)));
            long long go = (long long)(m0 + r) * lda + k0 + (cj << 3);
            cp16(aH + so, Ah + go);
            cp16(aL + so, Al + go);
        }
#pragma unroll
        for (int c = tid; c < BN * 8; c += THREADS) {
            int r = c >> 3, cj = c & 7;
            uint32_t so = swz((uint32_t)((r << 7) + (cj << 4)));
            long long go = (long long)(n0 + r) * ldb + k0 + (cj << 3);
            cp16(bH + so, Bh + go);
            cp16(bL + so, Bl + go);
        }
    };

    float acc[4][4][4];
#pragma unroll
    for (int i = 0; i < 4; ++i)
#pragma unroll
        for (int j = 0; j < 4; ++j)
#pragma unroll
            for (int q = 0; q < 4; ++q) acc[i][j][q] = 0.0f;

    load(0); CP_COMMIT();
    if (nk > 1) { load(1); CP_COMMIT(); }

    for (int it = 0; it < nk; ++it) {
        // stage `it` resident: allow 1 pending group (stage it+1) except at tail
        if (it + 1 < nk) { CP_WAIT(1); }
        else             { CP_WAIT(0); }
        __syncthreads();          // single barrier: publishes stage `it`, frees stage (it+2)%3
        if (it + 2 < nk) { load(it + 2); CP_COMMIT(); }   // overlaps with compute below

        uint32_t aH = st0 + (uint32_t)(it % 3) * STAGE, aL = aH + AST, bH = aL + AST, bL = bH + BST;
#pragma unroll
        for (int k16 = 0; k16 < 4; ++k16) {
            uint32_t ah[4][4], al[4][4], bh[4][2], bl[4][2];
#pragma unroll
            for (int mi = 0; mi < 4; ++mi) {
                uint32_t byte = (uint32_t)((wm0 + mi * 16 + (lid & 15)) << 7)
                              + (uint32_t)((k16 * 2 + (lid >> 4)) << 4);
                uint32_t so = swz(byte);
                ldm4(ah[mi], aH + so);
                ldm4(al[mi], aL + so);
            }
#pragma unroll
            for (int np = 0; np < 2; ++np) {   // paired ldm4: two n8-tiles per load
                uint32_t tb[4], tl[4];
                int row = wn0 + np * 16 + ((lid >> 4) << 3) + (lid & 7);
                int chunk = k16 * 2 + ((lid >> 3) & 1);
                uint32_t so = swz((uint32_t)((row << 7) + (chunk << 4)));
                ldm4(tb, bH + so);
                ldm4(tl, bL + so);
                bh[np * 2][0] = tb[0]; bh[np * 2][1] = tb[1];
                bh[np * 2 + 1][0] = tb[2]; bh[np * 2 + 1][1] = tb[3];
                bl[np * 2][0] = tl[0]; bl[np * 2][1] = tl[1];
                bl[np * 2 + 1][0] = tl[2]; bl[np * 2 + 1][1] = tl[3];
            }
#pragma unroll
            for (int mi = 0; mi < 4; ++mi)
#pragma unroll
                for (int ni = 0; ni < 4; ++ni) mma16816(acc[mi][ni], ah[mi], bh[ni]);
#pragma unroll
            for (int mi = 0; mi < 4; ++mi)
#pragma unroll
                for (int ni = 0; ni < 4; ++ni) mma16816(acc[mi][ni], ah[mi], bl[ni]);
#pragma unroll
            for (int mi = 0; mi < 4; ++mi)
#pragma unroll
                for (int ni = 0; ni < 4; ++ni) mma16816(acc[mi][ni], al[mi], bh[ni]);
        }
    }

#pragma unroll
    for (int mi = 0; mi < 4; ++mi) {
        const int gm = m0 + wm0 + mi * 16 + (lid >> 2);
#pragma unroll
        for (int ni = 0; ni < 4; ++ni) {
            const int gn = n0 + wn0 + ni * 8 + ((lid & 3) << 1);
            float v0 = acc[mi][ni][0] * alpha, v1 = acc[mi][ni][1] * alpha;
            float v2 = acc[mi][ni][2] * alpha, v3 = acc[mi][ni][3] * alpha;
            if (BIAS) {
                float b0 = bias[gn], b1 = bias[gn + 1];
                v0 += b0; v1 += b1; v2 += b0; v3 += b1;
            }
            if (RELU) {
                v0 = fmaxf(v0, 0.0f); v1 = fmaxf(v1, 0.0f);
                v2 = fmaxf(v2, 0.0f); v3 = fmaxf(v3, 0.0f);
            }
            if (WF32) {
                float2* p0 = reinterpret_cast<float2*>(Cf + cOff + (long long)gm * ldc + gn);
                float2* p1 = reinterpret_cast<float2*>(Cf + cOff + (long long)(gm + 8) * ldc + gn);
                *p0 = make_float2(v0, v1);
                *p1 = make_float2(v2, v3);
            } else {
                *reinterpret_cast<uint32_t*>(Ch + cOff + (long long)gm * ldc + gn)       = packhl(v0, v1, true);
                *reinterpret_cast<uint32_t*>(Cl + cOff + (long long)gm * ldc + gn)       = packhl(v0, v1, false);
                *reinterpret_cast<uint32_t*>(Ch + cOff + (long long)(gm + 8) * ldc + gn) = packhl(v2, v3, true);
                *reinterpret_cast<uint32_t*>(Cl + cOff + (long long)(gm + 8) * ldc + gn) = packhl(v2, v3, false);
            }
        }
    }
}

// ---------------------------------------------------------------------------
// Flash attention (unchanged R10 winner): per CTA one (b,h) x 128 q-rows.
// ---------------------------------------------------------------------------
__global__ __launch_bounds__(256)
void flash_attn(const bf16* __restrict__ qkvh, const bf16* __restrict__ qkvl,
                bf16* __restrict__ oh, bf16* __restrict__ ol)
{
    constexpr int LDA = 3072;
    extern __shared__ char smem[];
    const uint32_t sQh = (smem_u32(smem) + 127u) & ~127u;
    const uint32_t sQl = sQh + 16384;
    const uint32_t sKV = sQl + 16384;

    const int tid = threadIdx.x, wid = tid >> 5, lid = tid & 31;
    const int q0 = blockIdx.x * 128;
    const int z = blockIdx.y, b = z >> 4, h = z & 15;
    const long long base = (long long)b * 2048 * LDA + h * 64;
    const bf16* Qh = qkvh + base;        const bf16* Ql = qkvl + base;
    const bf16* Kh = qkvh + base + 1024; const bf16* Kl = qkvl + base + 1024;
    const bf16* Vh = qkvh + base + 2048; const bf16* Vl = qkvl + base + 2048;

    auto loadQ = [&]() {
#pragma unroll
        for (int i = 0; i < 4; ++i) {
            int c = tid + i * 256; int r = c >> 3, cj = c & 7;
            uint32_t so = swz((uint32_t)((r << 7) + (cj << 4)));
            long long go = (long long)(q0 + r) * LDA + (cj << 3);
            cp16(sQh + so, Qh + go);
            cp16(sQl + so, Ql + go);
        }
    };
    auto loadKV = [&](int t) {
        uint32_t st = sKV + (uint32_t)(t & 1) * 65536u;
        const int kr = t * 128;
#pragma unroll
        for (int i = 0; i < 4; ++i) {
            int c = tid + i * 256; int r = c >> 3, cj = c & 7;
            uint32_t so = swz((uint32_t)((r << 7) + (cj << 4)));
            long long go = (long long)(kr + r) * LDA + (cj << 3);
            cp16(st + so,          Kh + go);
            cp16(st + 16384 + so,  Kl + go);
            cp16(st + 32768 + so,  Vh + go);
            cp16(st + 49152 + so,  Vl + go);
        }
    };

    const int wq = wid * 16;
    float oacc[8][4];
#pragma unroll
    for (int n = 0; n < 8; ++n)
#pragma unroll
        for (int q = 0; q < 4; ++q) oacc[n][q] = 0.0f;
    float m0r = -1e30f, m1r = -1e30f, l0 = 0.0f, l1 = 0.0f;
    uint32_t qah[4][4], qal[4][4];

    loadQ(); loadKV(0); CP_COMMIT();

    for (int t = 0; t < 16; ++t) {
        if (t + 1 < 16) { loadKV(t + 1); CP_COMMIT(); CP_WAIT(1); }
        else            { CP_WAIT(0); }
        __syncthreads();

        if (t == 0) {
#pragma unroll
            for (int k16 = 0; k16 < 4; ++k16) {
                uint32_t byte = (uint32_t)((wq + (lid & 15)) << 7)
                              + (uint32_t)((k16 * 2 + (lid >> 4)) << 4);
                uint32_t so = swz(byte);
                ldm4(qah[k16], sQh + so);
                ldm4(qal[k16], sQl + so);
            }
        }

        const uint32_t stK = sKV + (uint32_t)(t & 1) * 65536u;
        const uint32_t stV = stK + 32768;

        float sacc[16][4];
#pragma unroll
        for (int i = 0; i < 16; ++i)
#pragma unroll
            for (int q = 0; q < 4; ++q) sacc[i][q] = 0.0f;

        const int grp = lid >> 3, rowIn = lid & 7;
#pragma unroll
        for (int k16 = 0; k16 < 4; ++k16) {
#pragma unroll
            for (int np = 0; np < 8; ++np) {
                uint32_t bfh[4], bfl[4];
                int n = np * 16 + ((grp >> 1) << 3) + rowIn;
                int chunk = k16 * 2 + (grp & 1);
                uint32_t so = swz((uint32_t)((n << 7) + (chunk << 4)));
                ldm4(bfh, stK + so);
                ldm4(bfl, stK + 16384 + so);
                mma16816(sacc[np * 2],     qah[k16], bfh);
                mma16816(sacc[np * 2],     qah[k16], bfl);
                mma16816(sacc[np * 2],     qal[k16], bfh);
                mma16816(sacc[np * 2 + 1], qah[k16], bfh + 2);
                mma16816(sacc[np * 2 + 1], qah[k16], bfl + 2);
                mma16816(sacc[np * 2 + 1], qal[k16], bfh + 2);
            }
        }

        float mn0 = m0r, mn1 = m1r;
#pragma unroll
        for (int i = 0; i < 16; ++i) {
            sacc[i][0] *= 0.125f; sacc[i][1] *= 0.125f;
            sacc[i][2] *= 0.125f; sacc[i][3] *= 0.125f;
            mn0 = fmaxf(mn0, fmaxf(sacc[i][0], sacc[i][1]));
            mn1 = fmaxf(mn1, fmaxf(sacc[i][2], sacc[i][3]));
        }
        mn0 = fmaxf(mn0, __shfl_xor_sync(0xFFFFFFFFu, mn0, 1));
        mn0 = fmaxf(mn0, __shfl_xor_sync(0xFFFFFFFFu, mn0, 2));
        mn1 = fmaxf(mn1, __shfl_xor_sync(0xFFFFFFFFu, mn1, 1));
        mn1 = fmaxf(mn1, __shfl_xor_sync(0xFFFFFFFFu, mn1, 2));
        float a0 = fexp(m0r - mn0), a1 = fexp(m1r - mn1);
        m0r = mn0; m1r = mn1;
#pragma unroll
        for (int n = 0; n < 8; ++n) {
            oacc[n][0] *= a0; oacc[n][1] *= a0;
            oacc[n][2] *= a1; oacc[n][3] *= a1;
        }
        float rs0 = 0.0f, rs1 = 0.0f;

#pragma unroll
        for (int j = 0; j < 8; ++j) {
            float p0 = fexp(sacc[2 * j][0] - m0r), p1 = fexp(sacc[2 * j][1] - m0r);
            float p2 = fexp(sacc[2 * j][2] - m1r), p3 = fexp(sacc[2 * j][3] - m1r);
            float p4 = fexp(sacc[2 * j + 1][0] - m0r), p5 = fexp(sacc[2 * j + 1][1] - m0r);
            float p6 = fexp(sacc[2 * j + 1][2] - m1r), p7 = fexp(sacc[2 * j + 1][3] - m1r);
            rs0 += p0 + p1 + p4 + p5;
            rs1 += p2 + p3 + p6 + p7;
            uint32_t pah[4], pal[4];
            pah[0] = packhl(p0, p1, true);  pal[0] = packhl(p0, p1, false);
            pah[1] = packhl(p2, p3, true);  pal[1] = packhl(p2, p3, false);
            pah[2] = packhl(p4, p5, true);  pal[2] = packhl(p4, p5, false);
            pah[3] = packhl(p6, p7, true);  pal[3] = packhl(p6, p7, false);
#pragma unroll
            for (int hp = 0; hp < 4; ++hp) {
                uint32_t bfh[4], bfl[4];
                int key = j * 16 + ((grp & 1) << 3) + rowIn;
                int chunk = hp * 2 + (grp >> 1);
                uint32_t so = swz((uint32_t)((key << 7) + (chunk << 4)));
                ldm4t(bfh, stV + so);
                ldm4t(bfl, stV + 16384 + so);
                mma16816(oacc[hp * 2],     pah, bfh);
                mma16816(oacc[hp * 2],     pah, bfl);
                mma16816(oacc[hp * 2],     pal, bfh);
                mma16816(oacc[hp * 2 + 1], pah, bfh + 2);
                mma16816(oacc[hp * 2 + 1], pah, bfl + 2);
                mma16816(oacc[hp * 2 + 1], pal, bfh + 2);
            }
        }
        rs0 += __shfl_xor_sync(0xFFFFFFFFu, rs0, 1);
        rs0 += __shfl_xor_sync(0xFFFFFFFFu, rs0, 2);
        rs1 += __shfl_xor_sync(0xFFFFFFFFu, rs1, 1);
        rs1 += __shfl_xor_sync(0xFFFFFFFFu, rs1, 2);
        l0 = l0 * a0 + rs0;
        l1 = l1 * a1 + rs1;
        __syncthreads();
    }

    const float inv0 = 1.0f / l0, inv1 = 1.0f / l1;
    const int gm0 = b * 2048 + q0 + wq + (lid >> 2);
    const int gnb = h * 64 + ((lid & 3) << 1);
#pragma unroll
    for (int n = 0; n < 8; ++n) {
        float v0 = oacc[n][0] * inv0, v1 = oacc[n][1] * inv0;
        float v2 = oacc[n][2] * inv1, v3 = oacc[n][3] * inv1;
        int gn = gnb + n * 8;
        *reinterpret_cast<uint32_t*>(oh + (long long)gm0 * 1024 + gn)       = packhl(v0, v1, true);
        *reinterpret_cast<uint32_t*>(ol + (long long)gm0 * 1024 + gn)       = packhl(v0, v1, false);
        *reinterpret_cast<uint32_t*>(oh + (long long)(gm0 + 8) * 1024 + gn) = packhl(v2, v3, true);
        *reinterpret_cast<uint32_t*>(ol + (long long)(gm0 + 8) * 1024 + gn) = packhl(v2, v3, false);
    }
}

// ---------------- prep kernels ----------------
__global__ __launch_bounds__(256)
void tsplit_w(const float* __restrict__ in, bf16* __restrict__ oh, bf16* __restrict__ ol,
              int ldi, int ldo, long long ibs, long long obs)
{
    __shared__ float t[32][33];
    const int z = blockIdx.z;
    const float* ip = in + z * ibs;
    bf16 *ohp = oh + z * obs, *olp = ol + z * obs;
    const int r0 = blockIdx.x * 32, c0 = blockIdx.y * 32;
    const int tx = threadIdx.x & 31, ty = threadIdx.x >> 5;
#pragma unroll
    for (int j = 0; j < 32; j += 8)
        t[ty + j][tx] = ip[(long long)(r0 + ty + j) * ldi + c0 + tx];
    __syncthreads();
#pragma unroll
    for (int j = 0; j < 32; j += 8) {
        float v = t[tx][ty + j];
        bf16 hh = __float2bfloat16(v);
        long long o = (long long)(c0 + ty + j) * ldo + r0 + tx;
        ohp[o] = hh;
        olp[o] = __float2bfloat16(v - __bfloat162float(hh));
    }
}

__global__ void biaspack(const float* q, const float* k, const float* v, float* o)
{
    int i = blockIdx.x * 256 + threadIdx.x;
    if (i < 1024) o[i] = q[i];
    else if (i < 2048) o[i] = k[i - 1024];
    else if (i < 3072) o[i] = v[i - 2048];
}

__global__ __launch_bounds__(256)
void xsplit(const float* __restrict__ in, bf16* __restrict__ oh, bf16* __restrict__ ol, int n4)
{
    int i = blockIdx.x * 256 + threadIdx.x;
    if (i >= n4) return;
    float4 v = reinterpret_cast<const float4*>(in)[i];
    uint2 uh = { packhl(v.x, v.y, true),  packhl(v.z, v.w, true)  };
    uint2 ul = { packhl(v.x, v.y, false), packhl(v.z, v.w, false) };
    reinterpret_cast<uint2*>(oh)[i] = uh;
    reinterpret_cast<uint2*>(ol)[i] = ul;
}

template <bool SPLIT>
__global__ __launch_bounds__(256)
void add_ln(const float* __restrict__ x, const float* __restrict__ d,
            const float* __restrict__ g, const float* __restrict__ b,
            float* __restrict__ out, bf16* __restrict__ oh, bf16* __restrict__ ol)
{
    const long long row = blockIdx.x;
    const int tid = threadIdx.x;
    const float4* x4 = reinterpret_cast<const float4*>(x) + row * 256;
    const float4* d4 = reinterpret_cast<const float4*>(d) + row * 256;
    float4 xv = x4[tid], dv = d4[tid], v;
    v.x = xv.x + dv.x; v.y = xv.y + dv.y; v.z = xv.z + dv.z; v.w = xv.w + dv.w;

    __shared__ float rs[256], rq[256];
    rs[tid] = v.x + v.y + v.z + v.w;
    rq[tid] = v.x * v.x + v.y * v.y + v.z * v.z + v.w * v.w;
    __syncthreads();
    for (int o = 128; o > 0; o >>= 1) {
        if (tid < o) { rs[tid] += rs[tid + o]; rq[tid] += rq[tid + o]; }
        __syncthreads();
    }
    const float mean = rs[0] * (1.0f / kD);
    const float rstd = rsqrtf(rq[0] * (1.0f / kD) - mean * mean + kEps);

    float4 gv = reinterpret_cast<const float4*>(g)[tid];
    float4 bv = reinterpret_cast<const float4*>(b)[tid];
    float4 ov;
    ov.x = (v.x - mean) * rstd * gv.x + bv.x;
    ov.y = (v.y - mean) * rstd * gv.y + bv.y;
    ov.z = (v.z - mean) * rstd * gv.z + bv.z;
    ov.w = (v.w - mean) * rstd * gv.w + bv.w;
    reinterpret_cast<float4*>(out)[row * 256 + tid] = ov;
    if (SPLIT) {
        uint2 uh = { packhl(ov.x, ov.y, true),  packhl(ov.z, ov.w, true)  };
        uint2 ul = { packhl(ov.x, ov.y, false), packhl(ov.z, ov.w, false) };
        reinterpret_cast<uint2*>(oh)[row * 256 + tid] = uh;
        reinterpret_cast<uint2*>(ol)[row * 256 + tid] = ul;
    }
}

// ---------------------------------------------------------------------------
extern "C" void kernel_launch(void* const* d_in, const int* in_sizes, int n_in,
                              void* d_out, int out_size)
{
    (void)in_sizes; (void)n_in; (void)out_size;
    const float* X  = (const float*)d_in[0];
    const float* Wq = (const float*)d_in[1];  const float* bq = (const float*)d_in[2];
    const float* Wk = (const float*)d_in[3];  const float* bk = (const float*)d_in[4];
    const float* Wv = (const float*)d_in[5];  const float* bv = (const float*)d_in[6];
    const float* Wo = (const float*)d_in[7];  const float* bo = (const float*)d_in[8];
    const float* l1g = (const float*)d_in[9]; const float* l1b = (const float*)d_in[10];
    const float* W1 = (const float*)d_in[11]; const float* b1 = (const float*)d_in[12];
    const float* W2 = (const float*)d_in[13]; const float* b2 = (const float*)d_in[14];
    const float* l2g = (const float*)d_in[15]; const float* l2b = (const float*)d_in[16];
    float* out = (float*)d_out;

    bf16 *wh, *wl, *xh, *xl, *qh, *ql, *ah, *al, *yh, *yl, *f1h, *f1l;
    float *bias, *pr, *y, *f2;
    cudaGetSymbolAddress((void**)&wh, g_wh);   cudaGetSymbolAddress((void**)&wl, g_wl);
    cudaGetSymbolAddress((void**)&bias, g_bias);
    cudaGetSymbolAddress((void**)&xh, g_xh);   cudaGetSymbolAddress((void**)&xl, g_xl);
    cudaGetSymbolAddress((void**)&qh, g_qh);   cudaGetSymbolAddress((void**)&ql, g_ql);
    cudaGetSymbolAddress((void**)&ah, g_ah);   cudaGetSymbolAddress((void**)&al, g_al);
    cudaGetSymbolAddress((void**)&pr, g_pr);   cudaGetSymbolAddress((void**)&y, g_y);
    cudaGetSymbolAddress((void**)&yh, g_yh);   cudaGetSymbolAddress((void**)&yl, g_yl);
    cudaGetSymbolAddress((void**)&f1h, g_f1h); cudaGetSymbolAddress((void**)&f1l, g_f1l);
    cudaGetSymbolAddress((void**)&f2, g_f2);

    constexpr int SM128 = 3 * (2 * 16384 + 2 * 16384) + 128;   // 196736 (3-stage)
    constexpr int FSM   = 2 * 16384 + 2 * 65536 + 128;         // 163968
    cudaFuncSetAttribute((const void*)hmma_gemm<128, true,  false, false>, cudaFuncAttributeMaxDynamicSharedMemorySize, SM128);
    cudaFuncSetAttribute((const void*)hmma_gemm<128, true,  false, true >, cudaFuncAttributeMaxDynamicSharedMemorySize, SM128);
    cudaFuncSetAttribute((const void*)hmma_gemm<128, true,  true,  false>, cudaFuncAttributeMaxDynamicSharedMemorySize, SM128);
    cudaFuncSetAttribute((const void*)flash_attn, cudaFuncAttributeMaxDynamicSharedMemorySize, FSM);

    // --- weight prep: transpose + hi/lo split ---
    tsplit_w<<<dim3(32, 2, 16), 256>>>(Wq, wh + WQKV,               wl + WQKV,               64, 1024, 65536, 65536);
    tsplit_w<<<dim3(32, 2, 16), 256>>>(Wk, wh + WQKV + 1024 * 1024, wl + WQKV + 1024 * 1024, 64, 1024, 65536, 65536);
    tsplit_w<<<dim3(32, 2, 16), 256>>>(Wv, wh + WQKV + 2048 * 1024, wl + WQKV + 2048 * 1024, 64, 1024, 65536, 65536);
    tsplit_w<<<dim3(32, 32, 1), 256>>>(Wo, wh + WO,  wl + WO,  1024, 1024, 0, 0);
    tsplit_w<<<dim3(32, 128, 1), 256>>>(W1, wh + W1O, wl + W1O, 4096, 1024, 0, 0);
    tsplit_w<<<dim3(128, 32, 1), 256>>>(W2, wh + W2O, wl + W2O, 1024, 4096, 0, 0);
    biaspack<<<12, 256>>>(bq, bk, bv, bias);
    xsplit<<<4096, 256>>>(X, xh, xl, kM * kD / 4);

    // --- fused QKV: [4096,1024] x [3072,1024]^T ---
    hmma_gemm<128, true, false, false><<<dim3(24, 32, 1), 256, SM128>>>(
        xh, xl, wh + WQKV, wl + WQKV, bias, nullptr, qh, ql,
        1024, 1024, 1024, 3072, 0, 0, 0, 0, 0, 0, 1, 1.0f);

    // --- flash attention: QK^T -> softmax -> PV fused ---
    flash_attn<<<dim3(16, 32), 256, FSM>>>(qh, ql, ah, al);

    // --- out projection ---
    hmma_gemm<128, true, false, true><<<dim3(8, 32, 1), 256, SM128>>>(
        ah, al, wh + WO, wl + WO, bo, pr, nullptr, nullptr,
        1024, 1024, 1024, 1024, 0, 0, 0, 0, 0, 0, 1, 1.0f);

    add_ln<true><<<kM, 256>>>(X, pr, l1g, l1b, y, yh, yl);

    // --- FFN1 (relu) ---
    hmma_gemm<128, true, true, false><<<dim3(32, 32, 1), 256, SM128>>>(
        yh, yl, wh + W1O, wl + W1O, b1, nullptr, f1h, f1l,
        1024, 1024, 1024, 4096, 0, 0, 0, 0, 0, 0, 1, 1.0f);

    // --- FFN2 ---
    hmma_gemm<128, true, false, true><<<dim3(8, 32, 1), 256, SM128>>>(
        f1h, f1l, wh + W2O, wl + W2O, b2, f2, nullptr, nullptr,
        4096, 4096, 4096, 1024, 0, 0, 0, 0, 0, 0, 1, 1.0f);

    add_ln<false><<<kM, 256>>>(y, f2, l2g, l2b, out, nullptr, nullptr);
}

// round 12
// speedup vs baseline: 4.1086x; 1.3099x over previous
#include <cuda_runtime.h>
#include <cuda_bf16.h>
#include <cuda_fp16.h>
#include <cstdint>

using bf16 = __nv_bfloat16;

constexpr int kB = 2, kS = 2048, kD = 1024, kH = 16, kHD = 64, kDFF = 4096;
constexpr int kM = kB * kS;
constexpr float kEps = 1e-5f;

constexpr long long WQKV = 0;            // [3072][1024]
constexpr long long WO   = 3145728;      // [1024][1024]
constexpr long long WTOT = 4194304;

__device__ bf16   g_wh[WTOT], g_wl[WTOT];          // QKV + Wo, bf16 hi/lo
__device__ __half g_w1h[4194304];                  // W1^T [4096][1024] fp16
__device__ __half g_w2h[4194304];                  // W2^T [1024][4096] fp16
__device__ float  g_bias[3072];
__device__ bf16   g_xh[4194304], g_xl[4194304];
__device__ bf16   g_qh[12582912], g_ql[12582912];  // fused QKV out [4096][3072]
__device__ bf16   g_ah[4194304], g_al[4194304];    // attn out [4096][1024]
__device__ float  g_pr[4194304];
__device__ float  g_y[4194304];
__device__ __half g_y16[4194304];                  // y fp16 (FFN1 input)
__device__ __half g_f1[16777216];                  // relu(ffn1) fp16 [4096][4096]
__device__ float  g_f2[4194304];

// ---------------- helpers ----------------
__device__ __forceinline__ uint32_t smem_u32(const void* p) {
    uint32_t a;
    asm("{ .reg .u64 t; cvta.to.shared.u64 t, %1; cvt.u32.u64 %0, t; }" : "=r"(a) : "l"(p));
    return a;
}
__device__ __forceinline__ void cp16(uint32_t s, const void* g) {
    asm volatile("cp.async.cg.shared.global [%0], [%1], 16;" :: "r"(s), "l"(g));
}
#define CP_COMMIT() asm volatile("cp.async.commit_group;" ::: "memory")
#define CP_WAIT(n)  asm volatile("cp.async.wait_group %0;" :: "n"(n) : "memory")
__device__ __forceinline__ uint32_t swz(uint32_t o) { return o ^ ((o >> 3) & 0x70); }

__device__ __forceinline__ void ldm4(uint32_t* r, uint32_t a) {
    asm volatile("ldmatrix.sync.aligned.m8n8.x4.shared.b16 {%0,%1,%2,%3}, [%4];"
                 : "=r"(r[0]), "=r"(r[1]), "=r"(r[2]), "=r"(r[3]) : "r"(a));
}
__device__ __forceinline__ void ldm4t(uint32_t* r, uint32_t a) {
    asm volatile("ldmatrix.sync.aligned.m8n8.x4.trans.shared.b16 {%0,%1,%2,%3}, [%4];"
                 : "=r"(r[0]), "=r"(r[1]), "=r"(r[2]), "=r"(r[3]) : "r"(a));
}
__device__ __forceinline__ void mma16816(float* c, const uint32_t* a, const uint32_t* b) {
    asm volatile("mma.sync.aligned.m16n8k16.row.col.f32.bf16.bf16.f32 "
                 "{%0,%1,%2,%3}, {%4,%5,%6,%7}, {%8,%9}, {%0,%1,%2,%3};"
                 : "+f"(c[0]), "+f"(c[1]), "+f"(c[2]), "+f"(c[3])
                 : "r"(a[0]), "r"(a[1]), "r"(a[2]), "r"(a[3]), "r"(b[0]), "r"(b[1]));
}
__device__ __forceinline__ void mma16816h(float* c, const uint32_t* a, const uint32_t* b) {
    asm volatile("mma.sync.aligned.m16n8k16.row.col.f32.f16.f16.f32 "
                 "{%0,%1,%2,%3}, {%4,%5,%6,%7}, {%8,%9}, {%0,%1,%2,%3};"
                 : "+f"(c[0]), "+f"(c[1]), "+f"(c[2]), "+f"(c[3])
                 : "r"(a[0]), "r"(a[1]), "r"(a[2]), "r"(a[3]), "r"(b[0]), "r"(b[1]));
}
__device__ __forceinline__ uint32_t packhl(float a, float b, bool hi) {
    __nv_bfloat162 t;
    bf16 ha = __float2bfloat16(a), hb = __float2bfloat16(b);
    if (hi) { t.x = ha; t.y = hb; }
    else { t.x = __float2bfloat16(a - __bfloat162float(ha)); t.y = __float2bfloat16(b - __bfloat162float(hb)); }
    return *reinterpret_cast<uint32_t*>(&t);
}
__device__ __forceinline__ uint32_t packh2(float a, float b) {
    __half2 t = __floats2half2_rn(a, b);
    return *reinterpret_cast<uint32_t*>(&t);
}
// fast exp on the FMA pipe (no MUFU)
__device__ __forceinline__ float fexp(float x) {
    x = fmaxf(x, -80.0f);
    float t = x * 1.4426950408889634f;
    int ni = __float2int_rn(t);
    float f = t - (float)ni;
    float p = 1.33355815e-3f;
    p = fmaf(p, f, 9.61812910e-3f);
    p = fmaf(p, f, 5.55041087e-2f);
    p = fmaf(p, f, 2.40226507e-1f);
    p = fmaf(p, f, 6.93147181e-1f);
    p = fmaf(p, f, 1.0f);
    return p * __int_as_float((ni + 127) << 23);
}

// ---------------------------------------------------------------------------
// HMMA split-bf16 GEMM (R11 winner, unchanged): 3-stage pipeline, one sync/iter.
// ---------------------------------------------------------------------------
template <int BN, bool BIAS, bool RELU, bool WF32>
__global__ __launch_bounds__(256)
void hmma_gemm(const bf16* __restrict__ Ah, const bf16* __restrict__ Al,
               const bf16* __restrict__ Bh, const bf16* __restrict__ Bl,
               const float* __restrict__ bias,
               float* __restrict__ Cf, bf16* __restrict__ Ch, bf16* __restrict__ Cl,
               int K, int lda, int ldb, int ldc,
               long long sA1, long long sA2, long long sB1, long long sB2,
               long long sC1, long long sC2, int bdiv, float alpha)
{
    constexpr int THREADS = 256;
    constexpr int WN = 4;
    constexpr int AST = 128 * 128;
    constexpr int BST = BN * 128;
    constexpr int STAGE = 2 * AST + 2 * BST;

    extern __shared__ char smem[];
    const uint32_t st0 = (smem_u32(smem) + 127u) & ~127u;

    const int tid = threadIdx.x, wid = tid >> 5, lid = tid & 31;
    const int z = blockIdx.z, zb = z / bdiv, zh = z - zb * bdiv;
    Ah += zb * sA1 + zh * sA2;  Al += zb * sA1 + zh * sA2;
    Bh += zb * sB1 + zh * sB2;  Bl += zb * sB1 + zh * sB2;
    const long long cOff = zb * sC1 + zh * sC2;
    const int m0 = blockIdx.y * 128, n0 = blockIdx.x * BN;
    const int wm0 = (wid / WN) * 64, wn0 = (wid % WN) * 32;

    const int nk = K >> 6;

    auto load = [&](int s) {
        uint32_t aH = st0 + (uint32_t)(s % 3) * STAGE, aL = aH + AST, bH = aL + AST, bL = bH + BST;
        const int k0 = s << 6;
#pragma unroll
        for (int c = tid; c < 1024; c += THREADS) {
            int r = c >> 3, cj = c & 7;
            uint32_t so = swz((uint32_t)((r << 7) + (cj << 4)));
            long long go = (long long)(m0 + r) * lda + k0 + (cj << 3);
            cp16(aH + so, Ah + go);
            cp16(aL + so, Al + go);
        }
#pragma unroll
        for (int c = tid; c < BN * 8; c += THREADS) {
            int r = c >> 3, cj = c & 7;
            uint32_t so = swz((uint32_t)((r << 7) + (cj << 4)));
            long long go = (long long)(n0 + r) * ldb + k0 + (cj << 3);
            cp16(bH + so, Bh + go);
            cp16(bL + so, Bl + go);
        }
    };

    float acc[4][4][4];
#pragma unroll
    for (int i = 0; i < 4; ++i)
#pragma unroll
        for (int j = 0; j < 4; ++j)
#pragma unroll
            for (int q = 0; q < 4; ++q) acc[i][j][q] = 0.0f;

    load(0); CP_COMMIT();
    if (nk > 1) { load(1); CP_COMMIT(); }

    for (int it = 0; it < nk; ++it) {
        if (it + 1 < nk) { CP_WAIT(1); }
        else             { CP_WAIT(0); }
        __syncthreads();
        if (it + 2 < nk) { load(it + 2); CP_COMMIT(); }

        uint32_t aH = st0 + (uint32_t)(it % 3) * STAGE, aL = aH + AST, bH = aL + AST, bL = bH + BST;
#pragma unroll
        for (int k16 = 0; k16 < 4; ++k16) {
            uint32_t ah[4][4], al[4][4], bh[4][2], bl[4][2];
#pragma unroll
            for (int mi = 0; mi < 4; ++mi) {
                uint32_t byte = (uint32_t)((wm0 + mi * 16 + (lid & 15)) << 7)
                              + (uint32_t)((k16 * 2 + (lid >> 4)) << 4);
                uint32_t so = swz(byte);
                ldm4(ah[mi], aH + so);
                ldm4(al[mi], aL + so);
            }
#pragma unroll
            for (int np = 0; np < 2; ++np) {
                uint32_t tb[4], tl[4];
                int row = wn0 + np * 16 + ((lid >> 4) << 3) + (lid & 7);
                int chunk = k16 * 2 + ((lid >> 3) & 1);
                uint32_t so = swz((uint32_t)((row << 7) + (chunk << 4)));
                ldm4(tb, bH + so);
                ldm4(tl, bL + so);
                bh[np * 2][0] = tb[0]; bh[np * 2][1] = tb[1];
                bh[np * 2 + 1][0] = tb[2]; bh[np * 2 + 1][1] = tb[3];
                bl[np * 2][0] = tl[0]; bl[np * 2][1] = tl[1];
                bl[np * 2 + 1][0] = tl[2]; bl[np * 2 + 1][1] = tl[3];
            }
#pragma unroll
            for (int mi = 0; mi < 4; ++mi)
#pragma unroll
                for (int ni = 0; ni < 4; ++ni) mma16816(acc[mi][ni], ah[mi], bh[ni]);
#pragma unroll
            for (int mi = 0; mi < 4; ++mi)
#pragma unroll
                for (int ni = 0; ni < 4; ++ni) mma16816(acc[mi][ni], ah[mi], bl[ni]);
#pragma unroll
            for (int mi = 0; mi < 4; ++mi)
#pragma unroll
                for (int ni = 0; ni < 4; ++ni) mma16816(acc[mi][ni], al[mi], bh[ni]);
        }
    }

#pragma unroll
    for (int mi = 0; mi < 4; ++mi) {
        const int gm = m0 + wm0 + mi * 16 + (lid >> 2);
#pragma unroll
        for (int ni = 0; ni < 4; ++ni) {
            const int gn = n0 + wn0 + ni * 8 + ((lid & 3) << 1);
            float v0 = acc[mi][ni][0] * alpha, v1 = acc[mi][ni][1] * alpha;
            float v2 = acc[mi][ni][2] * alpha, v3 = acc[mi][ni][3] * alpha;
            if (BIAS) {
                float b0 = bias[gn], b1 = bias[gn + 1];
                v0 += b0; v1 += b1; v2 += b0; v3 += b1;
            }
            if (RELU) {
                v0 = fmaxf(v0, 0.0f); v1 = fmaxf(v1, 0.0f);
                v2 = fmaxf(v2, 0.0f); v3 = fmaxf(v3, 0.0f);
            }
            if (WF32) {
                float2* p0 = reinterpret_cast<float2*>(Cf + cOff + (long long)gm * ldc + gn);
                float2* p1 = reinterpret_cast<float2*>(Cf + cOff + (long long)(gm + 8) * ldc + gn);
                *p0 = make_float2(v0, v1);
                *p1 = make_float2(v2, v3);
            } else {
                *reinterpret_cast<uint32_t*>(Ch + cOff + (long long)gm * ldc + gn)       = packhl(v0, v1, true);
                *reinterpret_cast<uint32_t*>(Cl + cOff + (long long)gm * ldc + gn)       = packhl(v0, v1, false);
                *reinterpret_cast<uint32_t*>(Ch + cOff + (long long)(gm + 8) * ldc + gn) = packhl(v2, v3, true);
                *reinterpret_cast<uint32_t*>(Cl + cOff + (long long)(gm + 8) * ldc + gn) = packhl(v2, v3, false);
            }
        }
    }
}

// ---------------------------------------------------------------------------
// Single-term fp16 GEMM for FFN: C = A*B^T (+bias, relu). 3-stage pipeline.
// A [M][K] fp16, B [N][K] fp16. Writes fp16 (f1) or fp32 (f2).
// ---------------------------------------------------------------------------
template <bool RELU, bool WF32>
__global__ __launch_bounds__(256)
void hmma_h1(const __half* __restrict__ A, const __half* __restrict__ B,
             const float* __restrict__ bias,
             float* __restrict__ Cf, __half* __restrict__ Ch,
             int K, int lda, int ldb, int ldc)
{
    constexpr int THREADS = 256;
    constexpr int WN = 4;
    constexpr int AST = 128 * 128;   // 128 rows x 64 halves = 128 B/row
    constexpr int STAGE = 2 * AST;   // A + B

    extern __shared__ char smem[];
    const uint32_t st0 = (smem_u32(smem) + 127u) & ~127u;

    const int tid = threadIdx.x, wid = tid >> 5, lid = tid & 31;
    const int m0 = blockIdx.y * 128, n0 = blockIdx.x * 128;
    const int wm0 = (wid / WN) * 64, wn0 = (wid % WN) * 32;

    const int nk = K >> 6;

    auto load = [&](int s) {
        uint32_t aS = st0 + (uint32_t)(s % 3) * STAGE, bS = aS + AST;
        const int k0 = s << 6;
#pragma unroll
        for (int c = tid; c < 1024; c += THREADS) {
            int r = c >> 3, cj = c & 7;
            uint32_t so = swz((uint32_t)((r << 7) + (cj << 4)));
            cp16(aS + so, A + (long long)(m0 + r) * lda + k0 + (cj << 3));
            cp16(bS + so, B + (long long)(n0 + r) * ldb + k0 + (cj << 3));
        }
    };

    float acc[4][4][4];
#pragma unroll
    for (int i = 0; i < 4; ++i)
#pragma unroll
        for (int j = 0; j < 4; ++j)
#pragma unroll
            for (int q = 0; q < 4; ++q) acc[i][j][q] = 0.0f;

    load(0); CP_COMMIT();
    if (nk > 1) { load(1); CP_COMMIT(); }

    for (int it = 0; it < nk; ++it) {
        if (it + 1 < nk) { CP_WAIT(1); }
        else             { CP_WAIT(0); }
        __syncthreads();
        if (it + 2 < nk) { load(it + 2); CP_COMMIT(); }

        uint32_t aS = st0 + (uint32_t)(it % 3) * STAGE, bS = aS + AST;
#pragma unroll
        for (int k16 = 0; k16 < 4; ++k16) {
            uint32_t ah[4][4], bh[4][2];
#pragma unroll
            for (int mi = 0; mi < 4; ++mi) {
                uint32_t byte = (uint32_t)((wm0 + mi * 16 + (lid & 15)) << 7)
                              + (uint32_t)((k16 * 2 + (lid >> 4)) << 4);
                ldm4(ah[mi], aS + swz(byte));
            }
#pragma unroll
            for (int np = 0; np < 2; ++np) {
                uint32_t tb[4];
                int row = wn0 + np * 16 + ((lid >> 4) << 3) + (lid & 7);
                int chunk = k16 * 2 + ((lid >> 3) & 1);
                ldm4(tb, bS + swz((uint32_t)((row << 7) + (chunk << 4))));
                bh[np * 2][0] = tb[0]; bh[np * 2][1] = tb[1];
                bh[np * 2 + 1][0] = tb[2]; bh[np * 2 + 1][1] = tb[3];
            }
#pragma unroll
            for (int mi = 0; mi < 4; ++mi)
#pragma unroll
                for (int ni = 0; ni < 4; ++ni) mma16816h(acc[mi][ni], ah[mi], bh[ni]);
        }
    }

#pragma unroll
    for (int mi = 0; mi < 4; ++mi) {
        const int gm = m0 + wm0 + mi * 16 + (lid >> 2);
#pragma unroll
        for (int ni = 0; ni < 4; ++ni) {
            const int gn = n0 + wn0 + ni * 8 + ((lid & 3) << 1);
            float b0 = bias[gn], b1 = bias[gn + 1];
            float v0 = acc[mi][ni][0] + b0, v1 = acc[mi][ni][1] + b1;
            float v2 = acc[mi][ni][2] + b0, v3 = acc[mi][ni][3] + b1;
            if (RELU) {
                v0 = fmaxf(v0, 0.0f); v1 = fmaxf(v1, 0.0f);
                v2 = fmaxf(v2, 0.0f); v3 = fmaxf(v3, 0.0f);
            }
            if (WF32) {
                *reinterpret_cast<float2*>(Cf + (long long)gm * ldc + gn)       = make_float2(v0, v1);
                *reinterpret_cast<float2*>(Cf + (long long)(gm + 8) * ldc + gn) = make_float2(v2, v3);
            } else {
                *reinterpret_cast<uint32_t*>(Ch + (long long)gm * ldc + gn)       = packh2(v0, v1);
                *reinterpret_cast<uint32_t*>(Ch + (long long)(gm + 8) * ldc + gn) = packh2(v2, v3);
            }
        }
    }
}

// ---------------------------------------------------------------------------
// Flash attention (unchanged R10/R11 winner)
// ---------------------------------------------------------------------------
__global__ __launch_bounds__(256)
void flash_attn(const bf16* __restrict__ qkvh, const bf16* __restrict__ qkvl,
                bf16* __restrict__ oh, bf16* __restrict__ ol)
{
    constexpr int LDA = 3072;
    extern __shared__ char smem[];
    const uint32_t sQh = (smem_u32(smem) + 127u) & ~127u;
    const uint32_t sQl = sQh + 16384;
    const uint32_t sKV = sQl + 16384;

    const int tid = threadIdx.x, wid = tid >> 5, lid = tid & 31;
    const int q0 = blockIdx.x * 128;
    const int z = blockIdx.y, b = z >> 4, h = z & 15;
    const long long base = (long long)b * 2048 * LDA + h * 64;
    const bf16* Qh = qkvh + base;        const bf16* Ql = qkvl + base;
    const bf16* Kh = qkvh + base + 1024; const bf16* Kl = qkvl + base + 1024;
    const bf16* Vh = qkvh + base + 2048; const bf16* Vl = qkvl + base + 2048;

    auto loadQ = [&]() {
#pragma unroll
        for (int i = 0; i < 4; ++i) {
            int c = tid + i * 256; int r = c >> 3, cj = c & 7;
            uint32_t so = swz((uint32_t)((r << 7) + (cj << 4)));
            long long go = (long long)(q0 + r) * LDA + (cj << 3);
            cp16(sQh + so, Qh + go);
            cp16(sQl + so, Ql + go);
        }
    };
    auto loadKV = [&](int t) {
        uint32_t st = sKV + (uint32_t)(t & 1) * 65536u;
        const int kr = t * 128;
#pragma unroll
        for (int i = 0; i < 4; ++i) {
            int c = tid + i * 256; int r = c >> 3, cj = c & 7;
            uint32_t so = swz((uint32_t)((r << 7) + (cj << 4)));
            long long go = (long long)(kr + r) * LDA + (cj << 3);
            cp16(st + so,          Kh + go);
            cp16(st + 16384 + so,  Kl + go);
            cp16(st + 32768 + so,  Vh + go);
            cp16(st + 49152 + so,  Vl + go);
        }
    };

    const int wq = wid * 16;
    float oacc[8][4];
#pragma unroll
    for (int n = 0; n < 8; ++n)
#pragma unroll
        for (int q = 0; q < 4; ++q) oacc[n][q] = 0.0f;
    float m0r = -1e30f, m1r = -1e30f, l0 = 0.0f, l1 = 0.0f;
    uint32_t qah[4][4], qal[4][4];

    loadQ(); loadKV(0); CP_COMMIT();

    for (int t = 0; t < 16; ++t) {
        if (t + 1 < 16) { loadKV(t + 1); CP_COMMIT(); CP_WAIT(1); }
        else            { CP_WAIT(0); }
        __syncthreads();

        if (t == 0) {
#pragma unroll
            for (int k16 = 0; k16 < 4; ++k16) {
                uint32_t byte = (uint32_t)((wq + (lid & 15)) << 7)
                              + (uint32_t)((k16 * 2 + (lid >> 4)) << 4);
                uint32_t so = swz(byte);
                ldm4(qah[k16], sQh + so);
                ldm4(qal[k16], sQl + so);
            }
        }

        const uint32_t stK = sKV + (uint32_t)(t & 1) * 65536u;
        const uint32_t stV = stK + 32768;

        float sacc[16][4];
#pragma unroll
        for (int i = 0; i < 16; ++i)
#pragma unroll
            for (int q = 0; q < 4; ++q) sacc[i][q] = 0.0f;

        const int grp = lid >> 3, rowIn = lid & 7;
#pragma unroll
        for (int k16 = 0; k16 < 4; ++k16) {
#pragma unroll
            for (int np = 0; np < 8; ++np) {
                uint32_t bfh[4], bfl[4];
                int n = np * 16 + ((grp >> 1) << 3) + rowIn;
                int chunk = k16 * 2 + (grp & 1);
                uint32_t so = swz((uint32_t)((n << 7) + (chunk << 4)));
                ldm4(bfh, stK + so);
                ldm4(bfl, stK + 16384 + so);
                mma16816(sacc[np * 2],     qah[k16], bfh);
                mma16816(sacc[np * 2],     qah[k16], bfl);
                mma16816(sacc[np * 2],     qal[k16], bfh);
                mma16816(sacc[np * 2 + 1], qah[k16], bfh + 2);
                mma16816(sacc[np * 2 + 1], qah[k16], bfl + 2);
                mma16816(sacc[np * 2 + 1], qal[k16], bfh + 2);
            }
        }

        float mn0 = m0r, mn1 = m1r;
#pragma unroll
        for (int i = 0; i < 16; ++i) {
            sacc[i][0] *= 0.125f; sacc[i][1] *= 0.125f;
            sacc[i][2] *= 0.125f; sacc[i][3] *= 0.125f;
            mn0 = fmaxf(mn0, fmaxf(sacc[i][0], sacc[i][1]));
            mn1 = fmaxf(mn1, fmaxf(sacc[i][2], sacc[i][3]));
        }
        mn0 = fmaxf(mn0, __shfl_xor_sync(0xFFFFFFFFu, mn0, 1));
        mn0 = fmaxf(mn0, __shfl_xor_sync(0xFFFFFFFFu, mn0, 2));
        mn1 = fmaxf(mn1, __shfl_xor_sync(0xFFFFFFFFu, mn1, 1));
        mn1 = fmaxf(mn1, __shfl_xor_sync(0xFFFFFFFFu, mn1, 2));
        float a0 = fexp(m0r - mn0), a1 = fexp(m1r - mn1);
        m0r = mn0; m1r = mn1;
#pragma unroll
        for (int n = 0; n < 8; ++n) {
            oacc[n][0] *= a0; oacc[n][1] *= a0;
            oacc[n][2] *= a1; oacc[n][3] *= a1;
        }
        float rs0 = 0.0f, rs1 = 0.0f;

#pragma unroll
        for (int j = 0; j < 8; ++j) {
            float p0 = fexp(sacc[2 * j][0] - m0r), p1 = fexp(sacc[2 * j][1] - m0r);
            float p2 = fexp(sacc[2 * j][2] - m1r), p3 = fexp(sacc[2 * j][3] - m1r);
            float p4 = fexp(sacc[2 * j + 1][0] - m0r), p5 = fexp(sacc[2 * j + 1][1] - m0r);
            float p6 = fexp(sacc[2 * j + 1][2] - m1r), p7 = fexp(sacc[2 * j + 1][3] - m1r);
            rs0 += p0 + p1 + p4 + p5;
            rs1 += p2 + p3 + p6 + p7;
            uint32_t pah[4], pal[4];
            pah[0] = packhl(p0, p1, true);  pal[0] = packhl(p0, p1, false);
            pah[1] = packhl(p2, p3, true);  pal[1] = packhl(p2, p3, false);
            pah[2] = packhl(p4, p5, true);  pal[2] = packhl(p4, p5, false);
            pah[3] = packhl(p6, p7, true);  pal[3] = packhl(p6, p7, false);
#pragma unroll
            for (int hp = 0; hp < 4; ++hp) {
                uint32_t bfh[4], bfl[4];
                int key = j * 16 + ((grp & 1) << 3) + rowIn;
                int chunk = hp * 2 + (grp >> 1);
                uint32_t so = swz((uint32_t)((key << 7) + (chunk << 4)));
                ldm4t(bfh, stV + so);
                ldm4t(bfl, stV + 16384 + so);
                mma16816(oacc[hp * 2],     pah, bfh);
                mma16816(oacc[hp * 2],     pah, bfl);
                mma16816(oacc[hp * 2],     pal, bfh);
                mma16816(oacc[hp * 2 + 1], pah, bfh + 2);
                mma16816(oacc[hp * 2 + 1], pah, bfl + 2);
                mma16816(oacc[hp * 2 + 1], pal, bfh + 2);
            }
        }
        rs0 += __shfl_xor_sync(0xFFFFFFFFu, rs0, 1);
        rs0 += __shfl_xor_sync(0xFFFFFFFFu, rs0, 2);
        rs1 += __shfl_xor_sync(0xFFFFFFFFu, rs1, 1);
        rs1 += __shfl_xor_sync(0xFFFFFFFFu, rs1, 2);
        l0 = l0 * a0 + rs0;
        l1 = l1 * a1 + rs1;
        __syncthreads();
    }

    const float inv0 = 1.0f / l0, inv1 = 1.0f / l1;
    const int gm0 = b * 2048 + q0 + wq + (lid >> 2);
    const int gnb = h * 64 + ((lid & 3) << 1);
#pragma unroll
    for (int n = 0; n < 8; ++n) {
        float v0 = oacc[n][0] * inv0, v1 = oacc[n][1] * inv0;
        float v2 = oacc[n][2] * inv1, v3 = oacc[n][3] * inv1;
        int gn = gnb + n * 8;
        *reinterpret_cast<uint32_t*>(oh + (long long)gm0 * 1024 + gn)       = packhl(v0, v1, true);
        *reinterpret_cast<uint32_t*>(ol + (long long)gm0 * 1024 + gn)       = packhl(v0, v1, false);
        *reinterpret_cast<uint32_t*>(oh + (long long)(gm0 + 8) * 1024 + gn) = packhl(v2, v3, true);
        *reinterpret_cast<uint32_t*>(ol + (long long)(gm0 + 8) * 1024 + gn) = packhl(v2, v3, false);
    }
}

// ---------------- prep kernels ----------------
// fused QKV weight transpose+split: z = w*16 + head, w in {0,1,2}
__global__ __launch_bounds__(256)
void tsplit_qkv(const float* __restrict__ wq, const float* __restrict__ wk,
                const float* __restrict__ wv, bf16* __restrict__ oh, bf16* __restrict__ ol)
{
    __shared__ float t[32][33];
    const int z = blockIdx.z, w = z >> 4, head = z & 15;
    const float* ip = (w == 0 ? wq : (w == 1 ? wk : wv)) + head * 65536;
    const long long ob = (long long)w * 1048576 + head * 65536;
    const int r0 = blockIdx.x * 32, c0 = blockIdx.y * 32;
    const int tx = threadIdx.x & 31, ty = threadIdx.x >> 5;
#pragma unroll
    for (int j = 0; j < 32; j += 8)
        t[ty + j][tx] = ip[(long long)(r0 + ty + j) * 64 + c0 + tx];
    __syncthreads();
#pragma unroll
    for (int j = 0; j < 32; j += 8) {
        float v = t[tx][ty + j];
        bf16 hh = __float2bfloat16(v);
        long long o = ob + (long long)(c0 + ty + j) * 1024 + r0 + tx;
        oh[o] = hh;
        ol[o] = __float2bfloat16(v - __bfloat162float(hh));
    }
}

__global__ __launch_bounds__(256)
void tsplit_w(const float* __restrict__ in, bf16* __restrict__ oh, bf16* __restrict__ ol,
              int ldi, int ldo)
{
    __shared__ float t[32][33];
    const int r0 = blockIdx.x * 32, c0 = blockIdx.y * 32;
    const int tx = threadIdx.x & 31, ty = threadIdx.x >> 5;
#pragma unroll
    for (int j = 0; j < 32; j += 8)
        t[ty + j][tx] = in[(long long)(r0 + ty + j) * ldi + c0 + tx];
    __syncthreads();
#pragma unroll
    for (int j = 0; j < 32; j += 8) {
        float v = t[tx][ty + j];
        bf16 hh = __float2bfloat16(v);
        long long o = (long long)(c0 + ty + j) * ldo + r0 + tx;
        oh[o] = hh;
        ol[o] = __float2bfloat16(v - __bfloat162float(hh));
    }
}

// fp32 -> fp16 transpose (single output)
__global__ __launch_bounds__(256)
void tsplit_h(const float* __restrict__ in, __half* __restrict__ o, int ldi, int ldo)
{
    __shared__ float t[32][33];
    const int r0 = blockIdx.x * 32, c0 = blockIdx.y * 32;
    const int tx = threadIdx.x & 31, ty = threadIdx.x >> 5;
#pragma unroll
    for (int j = 0; j < 32; j += 8)
        t[ty + j][tx] = in[(long long)(r0 + ty + j) * ldi + c0 + tx];
    __syncthreads();
#pragma unroll
    for (int j = 0; j < 32; j += 8)
        o[(long long)(c0 + ty + j) * ldo + r0 + tx] = __float2half(t[tx][ty + j]);
}

// fused X split + bias pack (extra block handles bias)
__global__ __launch_bounds__(256)
void xsplit_bias(const float* __restrict__ in, bf16* __restrict__ oh, bf16* __restrict__ ol,
                 int n4, const float* __restrict__ bq, const float* __restrict__ bk,
                 const float* __restrict__ bv, float* __restrict__ bias)
{
    if ((int)blockIdx.x == n4 / 256) {
        for (int i = threadIdx.x; i < 3072; i += 256) {
            if (i < 1024) bias[i] = bq[i];
            else if (i < 2048) bias[i] = bk[i - 1024];
            else bias[i] = bv[i - 2048];
        }
        return;
    }
    int i = blockIdx.x * 256 + threadIdx.x;
    float4 v = reinterpret_cast<const float4*>(in)[i];
    uint2 uh = { packhl(v.x, v.y, true),  packhl(v.z, v.w, true)  };
    uint2 ul = { packhl(v.x, v.y, false), packhl(v.z, v.w, false) };
    reinterpret_cast<uint2*>(oh)[i] = uh;
    reinterpret_cast<uint2*>(ol)[i] = ul;
}

template <bool H16>
__global__ __launch_bounds__(256)
void add_ln(const float* __restrict__ x, const float* __restrict__ d,
            const float* __restrict__ g, const float* __restrict__ b,
            float* __restrict__ out, __half* __restrict__ o16)
{
    const long long row = blockIdx.x;
    const int tid = threadIdx.x;
    const float4* x4 = reinterpret_cast<const float4*>(x) + row * 256;
    const float4* d4 = reinterpret_cast<const float4*>(d) + row * 256;
    float4 xv = x4[tid], dv = d4[tid], v;
    v.x = xv.x + dv.x; v.y = xv.y + dv.y; v.z = xv.z + dv.z; v.w = xv.w + dv.w;

    __shared__ float rs[256], rq[256];
    rs[tid] = v.x + v.y + v.z + v.w;
    rq[tid] = v.x * v.x + v.y * v.y + v.z * v.z + v.w * v.w;
    __syncthreads();
    for (int o = 128; o > 0; o >>= 1) {
        if (tid < o) { rs[tid] += rs[tid + o]; rq[tid] += rq[tid + o]; }
        __syncthreads();
    }
    const float mean = rs[0] * (1.0f / kD);
    const float rstd = rsqrtf(rq[0] * (1.0f / kD) - mean * mean + kEps);

    float4 gv = reinterpret_cast<const float4*>(g)[tid];
    float4 bv = reinterpret_cast<const float4*>(b)[tid];
    float4 ov;
    ov.x = (v.x - mean) * rstd * gv.x + bv.x;
    ov.y = (v.y - mean) * rstd * gv.y + bv.y;
    ov.z = (v.z - mean) * rstd * gv.z + bv.z;
    ov.w = (v.w - mean) * rstd * gv.w + bv.w;
    reinterpret_cast<float4*>(out)[row * 256 + tid] = ov;
    if (H16) {
        uint2 u = { packh2(ov.x, ov.y), packh2(ov.z, ov.w) };
        reinterpret_cast<uint2*>(o16)[row * 256 + tid] = u;
    }
}

// ---------------------------------------------------------------------------
extern "C" void kernel_launch(void* const* d_in, const int* in_sizes, int n_in,
                              void* d_out, int out_size)
{
    (void)in_sizes; (void)n_in; (void)out_size;
    const float* X  = (const float*)d_in[0];
    const float* Wq = (const float*)d_in[1];  const float* bq = (const float*)d_in[2];
    const float* Wk = (const float*)d_in[3];  const float* bk = (const float*)d_in[4];
    const float* Wv = (const float*)d_in[5];  const float* bv = (const float*)d_in[6];
    const float* Wo = (const float*)d_in[7];  const float* bo = (const float*)d_in[8];
    const float* l1g = (const float*)d_in[9]; const float* l1b = (const float*)d_in[10];
    const float* W1 = (const float*)d_in[11]; const float* b1 = (const float*)d_in[12];
    const float* W2 = (const float*)d_in[13]; const float* b2 = (const float*)d_in[14];
    const float* l2g = (const float*)d_in[15]; const float* l2b = (const float*)d_in[16];
    float* out = (float*)d_out;

    bf16 *wh, *wl, *xh, *xl, *qh, *ql, *ah, *al;
    __half *w1h, *w2h, *y16, *f1;
    float *bias, *pr, *y, *f2;
    cudaGetSymbolAddress((void**)&wh, g_wh);   cudaGetSymbolAddress((void**)&wl, g_wl);
    cudaGetSymbolAddress((void**)&w1h, g_w1h); cudaGetSymbolAddress((void**)&w2h, g_w2h);
    cudaGetSymbolAddress((void**)&bias, g_bias);
    cudaGetSymbolAddress((void**)&xh, g_xh);   cudaGetSymbolAddress((void**)&xl, g_xl);
    cudaGetSymbolAddress((void**)&qh, g_qh);   cudaGetSymbolAddress((void**)&ql, g_ql);
    cudaGetSymbolAddress((void**)&ah, g_ah);   cudaGetSymbolAddress((void**)&al, g_al);
    cudaGetSymbolAddress((void**)&pr, g_pr);   cudaGetSymbolAddress((void**)&y, g_y);
    cudaGetSymbolAddress((void**)&y16, g_y16); cudaGetSymbolAddress((void**)&f1, g_f1);
    cudaGetSymbolAddress((void**)&f2, g_f2);

    constexpr int SM128 = 3 * (2 * 16384 + 2 * 16384) + 128;   // 196736
    constexpr int SMH   = 3 * (2 * 16384) + 128;               //  98432
    constexpr int FSM   = 2 * 16384 + 2 * 65536 + 128;         // 163968
    cudaFuncSetAttribute((const void*)hmma_gemm<128, true,  false, false>, cudaFuncAttributeMaxDynamicSharedMemorySize, SM128);
    cudaFuncSetAttribute((const void*)hmma_gemm<128, true,  false, true >, cudaFuncAttributeMaxDynamicSharedMemorySize, SM128);
    cudaFuncSetAttribute((const void*)hmma_h1<true,  false>, cudaFuncAttributeMaxDynamicSharedMemorySize, SMH);
    cudaFuncSetAttribute((const void*)hmma_h1<false, true >, cudaFuncAttributeMaxDynamicSharedMemorySize, SMH);
    cudaFuncSetAttribute((const void*)flash_attn, cudaFuncAttributeMaxDynamicSharedMemorySize, FSM);

    // --- prep: exactly 5 launches so ncu (-s 5) captures the QKV GEMM ---
    tsplit_qkv<<<dim3(32, 2, 48), 256>>>(Wq, Wk, Wv, wh + WQKV, wl + WQKV);
    tsplit_w<<<dim3(32, 32, 1), 256>>>(Wo, wh + WO, wl + WO, 1024, 1024);
    tsplit_h<<<dim3(32, 128, 1), 256>>>(W1, w1h, 4096, 1024);
    tsplit_h<<<dim3(128, 32, 1), 256>>>(W2, w2h, 1024, 4096);
    xsplit_bias<<<4097, 256>>>(X, xh, xl, kM * kD / 4, bq, bk, bv, bias);

    // --- fused QKV (bf16 3-term): [4096,1024] x [3072,1024]^T ---
    hmma_gemm<128, true, false, false><<<dim3(24, 32, 1), 256, SM128>>>(
        xh, xl, wh + WQKV, wl + WQKV, bias, nullptr, qh, ql,
        1024, 1024, 1024, 3072, 0, 0, 0, 0, 0, 0, 1, 1.0f);

    // --- flash attention ---
    flash_attn<<<dim3(16, 32), 256, FSM>>>(qh, ql, ah, al);

    // --- out projection (bf16 3-term) ---
    hmma_gemm<128, true, false, true><<<dim3(8, 32, 1), 256, SM128>>>(
        ah, al, wh + WO, wl + WO, bo, pr, nullptr, nullptr,
        1024, 1024, 1024, 1024, 0, 0, 0, 0, 0, 0, 1, 1.0f);

    add_ln<true><<<kM, 256>>>(X, pr, l1g, l1b, y, y16);

    // --- FFN1 (fp16 1-term, relu): [4096,1024] x [4096,1024]^T ---
    hmma_h1<true, false><<<dim3(32, 32, 1), 256, SMH>>>(
        y16, w1h, b1, nullptr, f1, 1024, 1024, 1024, 4096);

    // --- FFN2 (fp16 1-term): [4096,4096] x [1024,4096]^T ---
    hmma_h1<false, true><<<dim3(8, 32, 1), 256, SMH>>>(
        f1, w2h, b2, f2, nullptr, 4096, 4096, 4096, 1024);

    add_ln<false><<<kM, 256>>>(y, f2, l2g, l2b, out, nullptr);
}

// round 15
// speedup vs baseline: 6.5495x; 1.5941x over previous
#include <cuda_runtime.h>
#include <cuda_fp16.h>
#include <cstdint>

constexpr int kB = 2, kS = 2048, kD = 1024, kH = 16, kHD = 64, kDFF = 4096;
constexpr int kM = kB * kS;
constexpr float kEps = 1e-5f;

constexpr long long WQKV = 0;            // [3072][1024]
constexpr long long WO   = 3145728;      // [1024][1024]

__device__ __half g_w16[4194304];                  // QKV^T + Wo^T fp16
__device__ __half g_w1h[4194304];                  // W1^T [4096][1024]
__device__ __half g_w2h[4194304];                  // W2^T [1024][4096]
__device__ float  g_bias[3072];
__device__ __half g_x16[4194304];                  // X fp16
__device__ __half g_qkv16[12582912];               // QKV out [4096][3072]
__device__ __half g_a16[4194304];                  // attn out [4096][1024]
__device__ float  g_pr[4194304];
__device__ float  g_y[4194304];
__device__ __half g_y16[4194304];
__device__ __half g_f1[16777216];                  // relu(ffn1) [4096][4096]
__device__ float  g_f2[4194304];

// ---------------- helpers ----------------
__device__ __forceinline__ uint32_t smem_u32(const void* p) {
    uint32_t a;
    asm("{ .reg .u64 t; cvta.to.shared.u64 t, %1; cvt.u32.u64 %0, t; }" : "=r"(a) : "l"(p));
    return a;
}
__device__ __forceinline__ void cp16(uint32_t s, const void* g) {
    asm volatile("cp.async.cg.shared.global [%0], [%1], 16;" :: "r"(s), "l"(g));
}
#define CP_COMMIT() asm volatile("cp.async.commit_group;" ::: "memory")
#define CP_WAIT(n)  asm volatile("cp.async.wait_group %0;" :: "n"(n) : "memory")
__device__ __forceinline__ uint32_t swz(uint32_t o) { return o ^ ((o >> 3) & 0x70); }

__device__ __forceinline__ void ldm4(uint32_t* r, uint32_t a) {
    asm volatile("ldmatrix.sync.aligned.m8n8.x4.shared.b16 {%0,%1,%2,%3}, [%4];"
                 : "=r"(r[0]), "=r"(r[1]), "=r"(r[2]), "=r"(r[3]) : "r"(a));
}
__device__ __forceinline__ void ldm4t(uint32_t* r, uint32_t a) {
    asm volatile("ldmatrix.sync.aligned.m8n8.x4.trans.shared.b16 {%0,%1,%2,%3}, [%4];"
                 : "=r"(r[0]), "=r"(r[1]), "=r"(r[2]), "=r"(r[3]) : "r"(a));
}
__device__ __forceinline__ void mma16816h(float* c, const uint32_t* a, const uint32_t* b) {
    asm volatile("mma.sync.aligned.m16n8k16.row.col.f32.f16.f16.f32 "
                 "{%0,%1,%2,%3}, {%4,%5,%6,%7}, {%8,%9}, {%0,%1,%2,%3};"
                 : "+f"(c[0]), "+f"(c[1]), "+f"(c[2]), "+f"(c[3])
                 : "r"(a[0]), "r"(a[1]), "r"(a[2]), "r"(a[3]), "r"(b[0]), "r"(b[1]));
}
__device__ __forceinline__ uint32_t packh2(float a, float b) {
    __half2 t = __floats2half2_rn(a, b);
    return *reinterpret_cast<uint32_t*>(&t);
}
// fast exp on the FMA pipe (no MUFU)
__device__ __forceinline__ float fexp(float x) {
    x = fmaxf(x, -80.0f);
    float t = x * 1.4426950408889634f;
    int ni = __float2int_rn(t);
    float f = t - (float)ni;
    float p = 1.33355815e-3f;
    p = fmaf(p, f, 9.61812910e-3f);
    p = fmaf(p, f, 5.55041087e-2f);
    p = fmaf(p, f, 2.40226507e-1f);
    p = fmaf(p, f, 6.93147181e-1f);
    p = fmaf(p, f, 1.0f);
    return p * __int_as_float((ni + 127) << 23);
}

// ---------------------------------------------------------------------------
// Single-term fp16 GEMM: C = A*B^T + bias (opt relu). 3-stage cp.async pipeline,
// one sync per K-iter. BM=BN=128, BK=64. 256 threads, warp tile 64x32.
// ---------------------------------------------------------------------------
template <bool RELU, bool WF32>
__global__ __launch_bounds__(256)
void hmma_h1(const __half* __restrict__ A, const __half* __restrict__ B,
             const float* __restrict__ bias,
             float* __restrict__ Cf, __half* __restrict__ Ch,
             int K, int lda, int ldb, int ldc)
{
    constexpr int THREADS = 256;
    constexpr int WN = 4;
    constexpr int AST = 128 * 128;   // 128 rows x 128 B
    constexpr int STAGE = 2 * AST;

    extern __shared__ char smem[];
    const uint32_t st0 = (smem_u32(smem) + 127u) & ~127u;

    const int tid = threadIdx.x, wid = tid >> 5, lid = tid & 31;
    const int m0 = blockIdx.y * 128, n0 = blockIdx.x * 128;
    const int wm0 = (wid / WN) * 64, wn0 = (wid % WN) * 32;

    const int nk = K >> 6;

    auto load = [&](int s) {
        uint32_t aS = st0 + (uint32_t)(s % 3) * STAGE, bS = aS + AST;
        const int k0 = s << 6;
#pragma unroll
        for (int c = tid; c < 1024; c += THREADS) {
            int r = c >> 3, cj = c & 7;
            uint32_t so = swz((uint32_t)((r << 7) + (cj << 4)));
            cp16(aS + so, A + (long long)(m0 + r) * lda + k0 + (cj << 3));
            cp16(bS + so, B + (long long)(n0 + r) * ldb + k0 + (cj << 3));
        }
    };

    float acc[4][4][4];
#pragma unroll
    for (int i = 0; i < 4; ++i)
#pragma unroll
        for (int j = 0; j < 4; ++j)
#pragma unroll
            for (int q = 0; q < 4; ++q) acc[i][j][q] = 0.0f;

    load(0); CP_COMMIT();
    if (nk > 1) { load(1); CP_COMMIT(); }

    for (int it = 0; it < nk; ++it) {
        if (it + 1 < nk) { CP_WAIT(1); }
        else             { CP_WAIT(0); }
        __syncthreads();
        if (it + 2 < nk) { load(it + 2); CP_COMMIT(); }

        uint32_t aS = st0 + (uint32_t)(it % 3) * STAGE, bS = aS + AST;
#pragma unroll
        for (int k16 = 0; k16 < 4; ++k16) {
            uint32_t ah[4][4], bh[4][2];
#pragma unroll
            for (int mi = 0; mi < 4; ++mi) {
                uint32_t byte = (uint32_t)((wm0 + mi * 16 + (lid & 15)) << 7)
                              + (uint32_t)((k16 * 2 + (lid >> 4)) << 4);
                ldm4(ah[mi], aS + swz(byte));
            }
#pragma unroll
            for (int np = 0; np < 2; ++np) {
                uint32_t tb[4];
                int row = wn0 + np * 16 + ((lid >> 4) << 3) + (lid & 7);
                int chunk = k16 * 2 + ((lid >> 3) & 1);
                ldm4(tb, bS + swz((uint32_t)((row << 7) + (chunk << 4))));
                bh[np * 2][0] = tb[0]; bh[np * 2][1] = tb[1];
                bh[np * 2 + 1][0] = tb[2]; bh[np * 2 + 1][1] = tb[3];
            }
#pragma unroll
            for (int mi = 0; mi < 4; ++mi)
#pragma unroll
                for (int ni = 0; ni < 4; ++ni) mma16816h(acc[mi][ni], ah[mi], bh[ni]);
        }
    }

#pragma unroll
    for (int mi = 0; mi < 4; ++mi) {
        const int gm = m0 + wm0 + mi * 16 + (lid >> 2);
#pragma unroll
        for (int ni = 0; ni < 4; ++ni) {
            const int gn = n0 + wn0 + ni * 8 + ((lid & 3) << 1);
            float b0 = bias[gn], b1 = bias[gn + 1];
            float v0 = acc[mi][ni][0] + b0, v1 = acc[mi][ni][1] + b1;
            float v2 = acc[mi][ni][2] + b0, v3 = acc[mi][ni][3] + b1;
            if (RELU) {
                v0 = fmaxf(v0, 0.0f); v1 = fmaxf(v1, 0.0f);
                v2 = fmaxf(v2, 0.0f); v3 = fmaxf(v3, 0.0f);
            }
            if (WF32) {
                *reinterpret_cast<float2*>(Cf + (long long)gm * ldc + gn)       = make_float2(v0, v1);
                *reinterpret_cast<float2*>(Cf + (long long)(gm + 8) * ldc + gn) = make_float2(v2, v3);
            } else {
                *reinterpret_cast<uint32_t*>(Ch + (long long)gm * ldc + gn)       = packh2(v0, v1);
                *reinterpret_cast<uint32_t*>(Ch + (long long)(gm + 8) * ldc + gn) = packh2(v2, v3);
            }
        }
    }
}

// ---------------------------------------------------------------------------
// Flash attention, fp16 single-term. Per CTA one (b,h) x 128 q-rows, 8 warps.
// K/V streamed in 128-key double-buffered tiles from fused QKV buffer.
// ---------------------------------------------------------------------------
__global__ __launch_bounds__(256)
void flash_attn(const __half* __restrict__ qkv, __half* __restrict__ o)
{
    constexpr int LDA = 3072;
    extern __shared__ char smem[];
    const uint32_t sQ  = (smem_u32(smem) + 127u) & ~127u;
    const uint32_t sKV = sQ + 16384;            // stage: K 16K + V 16K = 32K, x2

    const int tid = threadIdx.x, wid = tid >> 5, lid = tid & 31;
    const int q0 = blockIdx.x * 128;
    const int z = blockIdx.y, b = z >> 4, h = z & 15;
    const long long base = (long long)b * 2048 * LDA + h * 64;
    const __half* Q = qkv + base;
    const __half* K = qkv + base + 1024;
    const __half* V = qkv + base + 2048;

    auto loadQ = [&]() {
#pragma unroll
        for (int i = 0; i < 4; ++i) {
            int c = tid + i * 256; int r = c >> 3, cj = c & 7;
            uint32_t so = swz((uint32_t)((r << 7) + (cj << 4)));
            cp16(sQ + so, Q + (long long)(q0 + r) * LDA + (cj << 3));
        }
    };
    auto loadKV = [&](int t) {
        uint32_t st = sKV + (uint32_t)(t & 1) * 32768u;
        const int kr = t * 128;
#pragma unroll
        for (int i = 0; i < 4; ++i) {
            int c = tid + i * 256; int r = c >> 3, cj = c & 7;
            uint32_t so = swz((uint32_t)((r << 7) + (cj << 4)));
            long long go = (long long)(kr + r) * LDA + (cj << 3);
            cp16(st + so,         K + go);
            cp16(st + 16384 + so, V + go);
        }
    };

    const int wq = wid * 16;
    float oacc[8][4];
#pragma unroll
    for (int n = 0; n < 8; ++n)
#pragma unroll
        for (int q = 0; q < 4; ++q) oacc[n][q] = 0.0f;
    float m0r = -1e30f, m1r = -1e30f, l0 = 0.0f, l1 = 0.0f;
    uint32_t qa[4][4];

    loadQ(); loadKV(0); CP_COMMIT();

    for (int t = 0; t < 16; ++t) {
        if (t + 1 < 16) { loadKV(t + 1); CP_COMMIT(); CP_WAIT(1); }
        else            { CP_WAIT(0); }
        __syncthreads();

        if (t == 0) {
#pragma unroll
            for (int k16 = 0; k16 < 4; ++k16) {
                uint32_t byte = (uint32_t)((wq + (lid & 15)) << 7)
                              + (uint32_t)((k16 * 2 + (lid >> 4)) << 4);
                ldm4(qa[k16], sQ + swz(byte));
            }
        }

        const uint32_t stK = sKV + (uint32_t)(t & 1) * 32768u;
        const uint32_t stV = stK + 16384;

        // ---- S = Q K^T ----
        float sacc[16][4];
#pragma unroll
        for (int i = 0; i < 16; ++i)
#pragma unroll
            for (int q = 0; q < 4; ++q) sacc[i][q] = 0.0f;

        const int grp = lid >> 3, rowIn = lid & 7;
#pragma unroll
        for (int k16 = 0; k16 < 4; ++k16) {
#pragma unroll
            for (int np = 0; np < 8; ++np) {
                uint32_t bf[4];
                int n = np * 16 + ((grp >> 1) << 3) + rowIn;
                int chunk = k16 * 2 + (grp & 1);
                ldm4(bf, stK + swz((uint32_t)((n << 7) + (chunk << 4))));
                mma16816h(sacc[np * 2],     qa[k16], bf);
                mma16816h(sacc[np * 2 + 1], qa[k16], bf + 2);
            }
        }

        // ---- online softmax ----
        float mn0 = m0r, mn1 = m1r;
#pragma unroll
        for (int i = 0; i < 16; ++i) {
            sacc[i][0] *= 0.125f; sacc[i][1] *= 0.125f;
            sacc[i][2] *= 0.125f; sacc[i][3] *= 0.125f;
            mn0 = fmaxf(mn0, fmaxf(sacc[i][0], sacc[i][1]));
            mn1 = fmaxf(mn1, fmaxf(sacc[i][2], sacc[i][3]));
        }
        mn0 = fmaxf(mn0, __shfl_xor_sync(0xFFFFFFFFu, mn0, 1));
        mn0 = fmaxf(mn0, __shfl_xor_sync(0xFFFFFFFFu, mn0, 2));
        mn1 = fmaxf(mn1, __shfl_xor_sync(0xFFFFFFFFu, mn1, 1));
        mn1 = fmaxf(mn1, __shfl_xor_sync(0xFFFFFFFFu, mn1, 2));
        float a0 = fexp(m0r - mn0), a1 = fexp(m1r - mn1);
        m0r = mn0; m1r = mn1;
#pragma unroll
        for (int n = 0; n < 8; ++n) {
            oacc[n][0] *= a0; oacc[n][1] *= a0;
            oacc[n][2] *= a1; oacc[n][3] *= a1;
        }
        float rs0 = 0.0f, rs1 = 0.0f;

        // ---- P -> O += P V ----
#pragma unroll
        for (int j = 0; j < 8; ++j) {
            float p0 = fexp(sacc[2 * j][0] - m0r), p1 = fexp(sacc[2 * j][1] - m0r);
            float p2 = fexp(sacc[2 * j][2] - m1r), p3 = fexp(sacc[2 * j][3] - m1r);
            float p4 = fexp(sacc[2 * j + 1][0] - m0r), p5 = fexp(sacc[2 * j + 1][1] - m0r);
            float p6 = fexp(sacc[2 * j + 1][2] - m1r), p7 = fexp(sacc[2 * j + 1][3] - m1r);
            rs0 += p0 + p1 + p4 + p5;
            rs1 += p2 + p3 + p6 + p7;
            uint32_t pa[4];
            pa[0] = packh2(p0, p1); pa[1] = packh2(p2, p3);
            pa[2] = packh2(p4, p5); pa[3] = packh2(p6, p7);
#pragma unroll
            for (int hp = 0; hp < 4; ++hp) {
                uint32_t bf[4];
                int key = j * 16 + ((grp & 1) << 3) + rowIn;
                int chunk = hp * 2 + (grp >> 1);
                ldm4t(bf, stV + swz((uint32_t)((key << 7) + (chunk << 4))));
                mma16816h(oacc[hp * 2],     pa, bf);
                mma16816h(oacc[hp * 2 + 1], pa, bf + 2);
            }
        }
        rs0 += __shfl_xor_sync(0xFFFFFFFFu, rs0, 1);
        rs0 += __shfl_xor_sync(0xFFFFFFFFu, rs0, 2);
        rs1 += __shfl_xor_sync(0xFFFFFFFFu, rs1, 1);
        rs1 += __shfl_xor_sync(0xFFFFFFFFu, rs1, 2);
        l0 = l0 * a0 + rs0;
        l1 = l1 * a1 + rs1;
        __syncthreads();
    }

    const float inv0 = 1.0f / l0, inv1 = 1.0f / l1;
    const int gm0 = b * 2048 + q0 + wq + (lid >> 2);
    const int gnb = h * 64 + ((lid & 3) << 1);
#pragma unroll
    for (int n = 0; n < 8; ++n) {
        int gn = gnb + n * 8;
        *reinterpret_cast<uint32_t*>(o + (long long)gm0 * 1024 + gn) =
            packh2(oacc[n][0] * inv0, oacc[n][1] * inv0);
        *reinterpret_cast<uint32_t*>(o + (long long)(gm0 + 8) * 1024 + gn) =
            packh2(oacc[n][2] * inv1, oacc[n][3] * inv1);
    }
}

// ---------------- prep kernels ----------------
// QKV weights [H,D,HD] (x3) -> fp16 transposed rows [3072][1024]
__global__ __launch_bounds__(256)
void tsplit_qkv16(const float* __restrict__ wq, const float* __restrict__ wk,
                  const float* __restrict__ wv, __half* __restrict__ o)
{
    __shared__ float t[32][33];
    const int z = blockIdx.z, w = z >> 4, head = z & 15;
    const float* ip = (w == 0 ? wq : (w == 1 ? wk : wv)) + head * 65536;
    const long long ob = (long long)w * 1048576 + head * 65536;
    const int r0 = blockIdx.x * 32, c0 = blockIdx.y * 32;
    const int tx = threadIdx.x & 31, ty = threadIdx.x >> 5;
#pragma unroll
    for (int j = 0; j < 32; j += 8)
        t[ty + j][tx] = ip[(long long)(r0 + ty + j) * 64 + c0 + tx];
    __syncthreads();
#pragma unroll
    for (int j = 0; j < 32; j += 8)
        o[ob + (long long)(c0 + ty + j) * 1024 + r0 + tx] = __float2half(t[tx][ty + j]);
}

// generic fp32 [R][C] -> fp16 transposed [C][R]
__global__ __launch_bounds__(256)
void tsplit_h(const float* __restrict__ in, __half* __restrict__ o, int ldi, int ldo)
{
    __shared__ float t[32][33];
    const int r0 = blockIdx.x * 32, c0 = blockIdx.y * 32;
    const int tx = threadIdx.x & 31, ty = threadIdx.x >> 5;
#pragma unroll
    for (int j = 0; j < 32; j += 8)
        t[ty + j][tx] = in[(long long)(r0 + ty + j) * ldi + c0 + tx];
    __syncthreads();
#pragma unroll
    for (int j = 0; j < 32; j += 8)
        o[(long long)(c0 + ty + j) * ldo + r0 + tx] = __float2half(t[tx][ty + j]);
}

// X fp32 -> fp16 + bias pack (last block)
__global__ __launch_bounds__(256)
void xsplit_bias(const float* __restrict__ in, __half* __restrict__ o, int n4,
                 const float* __restrict__ bq, const float* __restrict__ bk,
                 const float* __restrict__ bv, float* __restrict__ bias)
{
    if ((int)blockIdx.x == n4 / 256) {
        for (int i = threadIdx.x; i < 3072; i += 256) {
            if (i < 1024) bias[i] = bq[i];
            else if (i < 2048) bias[i] = bk[i - 1024];
            else bias[i] = bv[i - 2048];
        }
        return;
    }
    int i = blockIdx.x * 256 + threadIdx.x;
    float4 v = reinterpret_cast<const float4*>(in)[i];
    uint2 u = { packh2(v.x, v.y), packh2(v.z, v.w) };
    reinterpret_cast<uint2*>(o)[i] = u;
}

template <bool H16>
__global__ __launch_bounds__(256)
void add_ln(const float* __restrict__ x, const float* __restrict__ d,
            const float* __restrict__ g, const float* __restrict__ b,
            float* __restrict__ out, __half* __restrict__ o16)
{
    const long long row = blockIdx.x;
    const int tid = threadIdx.x;
    const float4* x4 = reinterpret_cast<const float4*>(x) + row * 256;
    const float4* d4 = reinterpret_cast<const float4*>(d) + row * 256;
    float4 xv = x4[tid], dv = d4[tid], v;
    v.x = xv.x + dv.x; v.y = xv.y + dv.y; v.z = xv.z + dv.z; v.w = xv.w + dv.w;

    __shared__ float rs[256], rq[256];
    rs[tid] = v.x + v.y + v.z + v.w;
    rq[tid] = v.x * v.x + v.y * v.y + v.z * v.z + v.w * v.w;
    __syncthreads();
    for (int o = 128; o > 0; o >>= 1) {
        if (tid < o) { rs[tid] += rs[tid + o]; rq[tid] += rq[tid + o]; }
        __syncthreads();
    }
    const float mean = rs[0] * (1.0f / kD);
    const float rstd = rsqrtf(rq[0] * (1.0f / kD) - mean * mean + kEps);

    float4 gv = reinterpret_cast<const float4*>(g)[tid];
    float4 bv = reinterpret_cast<const float4*>(b)[tid];
    float4 ov;
    ov.x = (v.x - mean) * rstd * gv.x + bv.x;
    ov.y = (v.y - mean) * rstd * gv.y + bv.y;
    ov.z = (v.z - mean) * rstd * gv.z + bv.z;
    ov.w = (v.w - mean) * rstd * gv.w + bv.w;
    reinterpret_cast<float4*>(out)[row * 256 + tid] = ov;
    if (H16) {
        uint2 u = { packh2(ov.x, ov.y), packh2(ov.z, ov.w) };
        reinterpret_cast<uint2*>(o16)[row * 256 + tid] = u;
    }
}

// ---------------------------------------------------------------------------
extern "C" void kernel_launch(void* const* d_in, const int* in_sizes, int n_in,
                              void* d_out, int out_size)
{
    (void)in_sizes; (void)n_in; (void)out_size;
    const float* X  = (const float*)d_in[0];
    const float* Wq = (const float*)d_in[1];  const float* bq = (const float*)d_in[2];
    const float* Wk = (const float*)d_in[3];  const float* bk = (const float*)d_in[4];
    const float* Wv = (const float*)d_in[5];  const float* bv = (const float*)d_in[6];
    const float* Wo = (const float*)d_in[7];  const float* bo = (const float*)d_in[8];
    const float* l1g = (const float*)d_in[9]; const float* l1b = (const float*)d_in[10];
    const float* W1 = (const float*)d_in[11]; const float* b1 = (const float*)d_in[12];
    const float* W2 = (const float*)d_in[13]; const float* b2 = (const float*)d_in[14];
    const float* l2g = (const float*)d_in[15]; const float* l2b = (const float*)d_in[16];
    float* out = (float*)d_out;

    __half *w16, *w1h, *w2h, *x16, *qkv16, *a16, *y16, *f1;
    float *bias, *pr, *y, *f2;
    cudaGetSymbolAddress((void**)&w16, g_w16);
    cudaGetSymbolAddress((void**)&w1h, g_w1h); cudaGetSymbolAddress((void**)&w2h, g_w2h);
    cudaGetSymbolAddress((void**)&bias, g_bias);
    cudaGetSymbolAddress((void**)&x16, g_x16);
    cudaGetSymbolAddress((void**)&qkv16, g_qkv16);
    cudaGetSymbolAddress((void**)&a16, g_a16);
    cudaGetSymbolAddress((void**)&pr, g_pr);   cudaGetSymbolAddress((void**)&y, g_y);
    cudaGetSymbolAddress((void**)&y16, g_y16); cudaGetSymbolAddress((void**)&f1, g_f1);
    cudaGetSymbolAddress((void**)&f2, g_f2);

    constexpr int SMH  = 3 * (2 * 16384) + 128;      // 98432
    constexpr int FSM  = 16384 + 2 * 32768 + 128;    // 82048
    cudaFuncSetAttribute((const void*)hmma_h1<false, false>, cudaFuncAttributeMaxDynamicSharedMemorySize, SMH);
    cudaFuncSetAttribute((const void*)hmma_h1<false, true >, cudaFuncAttributeMaxDynamicSharedMemorySize, SMH);
    cudaFuncSetAttribute((const void*)hmma_h1<true,  false>, cudaFuncAttributeMaxDynamicSharedMemorySize, SMH);
    cudaFuncSetAttribute((const void*)flash_attn, cudaFuncAttributeMaxDynamicSharedMemorySize, FSM);

    // --- prep: exactly 5 launches so ncu (-s 5) lands on the QKV GEMM ---
    tsplit_qkv16<<<dim3(32, 2, 48), 256>>>(Wq, Wk, Wv, w16 + WQKV);
    tsplit_h<<<dim3(32, 32, 1), 256>>>(Wo, w16 + WO, 1024, 1024);
    tsplit_h<<<dim3(32, 128, 1), 256>>>(W1, w1h, 4096, 1024);
    tsplit_h<<<dim3(128, 32, 1), 256>>>(W2, w2h, 1024, 4096);
    xsplit_bias<<<4097, 256>>>(X, x16, kM * kD / 4, bq, bk, bv, bias);

    // --- fused QKV (fp16): [4096,1024] x [3072,1024]^T ---
    hmma_h1<false, false><<<dim3(24, 32, 1), 256, SMH>>>(
        x16, w16 + WQKV, bias, nullptr, qkv16, 1024, 1024, 1024, 3072);

    // --- flash attention (fp16) ---
    flash_attn<<<dim3(16, 32), 256, FSM>>>(qkv16, a16);

    // --- out projection (fp16 -> fp32) ---
    hmma_h1<false, true><<<dim3(8, 32, 1), 256, SMH>>>(
        a16, w16 + WO, bo, pr, nullptr, 1024, 1024, 1024, 1024);

    add_ln<true><<<kM, 256>>>(X, pr, l1g, l1b, y, y16);

    // --- FFN1 (fp16, relu) ---
    hmma_h1<true, false><<<dim3(32, 32, 1), 256, SMH>>>(
        y16, w1h, b1, nullptr, f1, 1024, 1024, 1024, 4096);

    // --- FFN2 (fp16 -> fp32) ---
    hmma_h1<false, true><<<dim3(8, 32, 1), 256, SMH>>>(
        f1, w2h, b2, f2, nullptr, 4096, 4096, 4096, 1024);

    add_ln<false><<<kM, 256>>>(y, f2, l2g, l2b, out, nullptr);
}